// round 2
// baseline (speedup 1.0000x reference)
#include <cuda_runtime.h>
#include <math.h>

#define B_    8
#define L_    8192
#define DM    128
#define DI    256
#define DS    16
#define DTR   8
#define NROWS (B_*L_)          // 65536
#define TC    64               // scan chunk length
#define NCH   (L_/TC)          // 128 chunks

// ---------------- scratch (device globals; no allocation allowed) ----------------
__device__ float g_xn [(size_t)NROWS*DM];     // layernorm output          33.5 MB
__device__ float g_xz [(size_t)NROWS*512];    // in_proj output (u|z)      134 MB
__device__ float g_u2 [(size_t)NROWS*DI];     // conv+silu output          67 MB
__device__ float g_dbc[(size_t)NROWS*40];     // x_proj output (dt|B|C)    10.5 MB
__device__ float g_dt [(size_t)NROWS*DI];     // softplus(dt)              67 MB
__device__ float g_y  [(size_t)NROWS*DI];     // scan output               67 MB
__device__ float g_dec[B_*NCH*DI*DS];         // chunk decay products      16.8 MB
__device__ float g_snd[B_*NCH*DI*DS];         // chunk end states          16.8 MB
__device__ float g_hin[B_*NCH*DI*DS];         // chunk init states         16.8 MB

// ---------------- init: h[b,l,d] = sum_c x[b,c,l]*proj_w[d,c] + proj_b[d] --------
__global__ void init_h_kernel(const float* __restrict__ x, const float* __restrict__ pw,
                              const float* __restrict__ pb, float* __restrict__ h) {
    int idx = blockIdx.x * blockDim.x + threadIdx.x;
    if (idx >= NROWS * DM) return;
    int d = idx & (DM - 1);
    int row = idx >> 7;
    int b = row >> 13;          // /L_
    int l = row & (L_ - 1);
    float acc = pb[d];
#pragma unroll
    for (int c = 0; c < 3; c++)
        acc += x[(b * 3 + c) * L_ + l] * pw[d * 3 + c];
    h[idx] = acc;
}

// ---------------- layernorm: warp per row of 128 ---------------------------------
__global__ void ln_kernel(const float* __restrict__ in, const float* __restrict__ w,
                          const float* __restrict__ bias, float* __restrict__ out,
                          int nrows) {
    int gwarp = (blockIdx.x * blockDim.x + threadIdx.x) >> 5;
    int lane  = threadIdx.x & 31;
    if (gwarp >= nrows) return;
    const float4 v = *reinterpret_cast<const float4*>(&in[(size_t)gwarp * DM + lane * 4]);
    float s = v.x + v.y + v.z + v.w;
#pragma unroll
    for (int o = 16; o; o >>= 1) s += __shfl_xor_sync(0xffffffffu, s, o);
    float mu = s * (1.0f / DM);
    float d0 = v.x - mu, d1 = v.y - mu, d2 = v.z - mu, d3 = v.w - mu;
    float q = d0 * d0 + d1 * d1 + d2 * d2 + d3 * d3;
#pragma unroll
    for (int o = 16; o; o >>= 1) q += __shfl_xor_sync(0xffffffffu, q, o);
    float r = rsqrtf(q * (1.0f / DM) + 1e-5f);
    const float4 wv = *reinterpret_cast<const float4*>(&w[lane * 4]);
    const float4 bv = *reinterpret_cast<const float4*>(&bias[lane * 4]);
    float4 o4;
    o4.x = d0 * r * wv.x + bv.x;
    o4.y = d1 * r * wv.y + bv.y;
    o4.z = d2 * r * wv.z + bv.z;
    o4.w = d3 * r * wv.w + bv.w;
    *reinterpret_cast<float4*>(&out[(size_t)gwarp * DM + lane * 4]) = o4;
}

// ---------------- generic fp32 GEMM: C[M,N] = A[M,K] * W[N,K]^T ------------------
// 128x128 tile, BK=16, 256 threads, 8x8 per thread. EPI=1: C += result (residual).
#define GBM 128
#define GBN 128
#define GBK 16
template <int EPI>
__global__ void gemm_kernel(const float* __restrict__ A, const float* __restrict__ W,
                            float* __restrict__ C, int M, int N, int K) {
    __shared__ float As[GBK][GBM + 4];
    __shared__ float Ws[GBK][GBN + 4];
    int tid = threadIdx.x;
    int tx = tid & 15;        // 0..15  (N dir)
    int ty = tid >> 4;        // 0..15  (M dir)
    int m0 = blockIdx.y * GBM;
    int n0 = blockIdx.x * GBN;

    float acc[8][8];
#pragma unroll
    for (int i = 0; i < 8; i++)
#pragma unroll
        for (int j = 0; j < 8; j++) acc[i][j] = 0.0f;

    for (int k0 = 0; k0 < K; k0 += GBK) {
#pragma unroll
        for (int r = 0; r < 2; r++) {
            int idx = tid + r * 256;           // 0..511
            int m = idx >> 2;                  // 0..127
            int kq = (idx & 3) * 4;            // 0,4,8,12
            float4 v = *reinterpret_cast<const float4*>(&A[(size_t)(m0 + m) * K + k0 + kq]);
            As[kq + 0][m] = v.x; As[kq + 1][m] = v.y;
            As[kq + 2][m] = v.z; As[kq + 3][m] = v.w;
        }
#pragma unroll
        for (int r = 0; r < 2; r++) {
            int idx = tid + r * 256;
            int n = idx >> 2;
            int kq = (idx & 3) * 4;
            float4 v = make_float4(0.f, 0.f, 0.f, 0.f);
            if (n0 + n < N)
                v = *reinterpret_cast<const float4*>(&W[(size_t)(n0 + n) * K + k0 + kq]);
            Ws[kq + 0][n] = v.x; Ws[kq + 1][n] = v.y;
            Ws[kq + 2][n] = v.z; Ws[kq + 3][n] = v.w;
        }
        __syncthreads();
#pragma unroll
        for (int kk = 0; kk < GBK; kk++) {
            float4 a0 = *reinterpret_cast<const float4*>(&As[kk][ty * 8]);
            float4 a1 = *reinterpret_cast<const float4*>(&As[kk][ty * 8 + 4]);
            float4 w0 = *reinterpret_cast<const float4*>(&Ws[kk][tx * 8]);
            float4 w1 = *reinterpret_cast<const float4*>(&Ws[kk][tx * 8 + 4]);
            float a[8] = {a0.x, a0.y, a0.z, a0.w, a1.x, a1.y, a1.z, a1.w};
            float w[8] = {w0.x, w0.y, w0.z, w0.w, w1.x, w1.y, w1.z, w1.w};
#pragma unroll
            for (int i = 0; i < 8; i++)
#pragma unroll
                for (int j = 0; j < 8; j++) acc[i][j] += a[i] * w[j];
        }
        __syncthreads();
    }
#pragma unroll
    for (int i = 0; i < 8; i++) {
        int m = m0 + ty * 8 + i;
#pragma unroll
        for (int j = 0; j < 8; j++) {
            int n = n0 + tx * 8 + j;
            if (n < N) {
                size_t off = (size_t)m * N + n;
                if (EPI == 1) C[off] += acc[i][j];
                else          C[off] = acc[i][j];
            }
        }
    }
}

// ---------------- causal depthwise conv1d (kernel 4) + silu ----------------------
__global__ void conv_silu_kernel(const float* __restrict__ xz, const float* __restrict__ cw,
                                 const float* __restrict__ cb, float* __restrict__ u2) {
    int idx = blockIdx.x * blockDim.x + threadIdx.x;
    if (idx >= NROWS * DI) return;
    int d = idx & (DI - 1);
    int row = idx >> 8;
    int l = row & (L_ - 1);
    float acc = cb[d];
#pragma unroll
    for (int k = 0; k < 4; k++) {
        int lk = l - 3 + k;
        if (lk >= 0)
            acc += xz[(size_t)(row - 3 + k) * 512 + d] * cw[d * 4 + k];
    }
    float sg = 1.0f / (1.0f + __expf(-acc));
    u2[idx] = acc * sg;
}

// ---------------- dt projection (K=8) + softplus ---------------------------------
__global__ void dt_kernel(const float* __restrict__ dbc, const float* __restrict__ dtw,
                          const float* __restrict__ dtb, float* __restrict__ dto) {
    __shared__ float dsh[8 * DTR];            // 8 rows x 8 dt_raw
    int tid = threadIdx.x;                    // 0..255 == d
    int row0 = blockIdx.x * 8;
    float wreg[DTR];
#pragma unroll
    for (int k = 0; k < DTR; k++) wreg[k] = dtw[tid * DTR + k];
    float breg = dtb[tid];
    if (tid < 64)
        dsh[tid] = dbc[(size_t)(row0 + (tid >> 3)) * 40 + (tid & 7)];
    __syncthreads();
#pragma unroll
    for (int r = 0; r < 8; r++) {
        float acc = breg;
#pragma unroll
        for (int k = 0; k < DTR; k++) acc += dsh[r * DTR + k] * wreg[k];
        float sp = (acc > 20.0f) ? acc : log1pf(__expf(acc));
        dto[(size_t)(row0 + r) * DI + tid] = sp;
    }
}

// ---------------- scan phase 1: per-chunk local scan (init=0) --------------------
__global__ void scan_ph1(const float* __restrict__ dt, const float* __restrict__ u2,
                         const float* __restrict__ dbc, const float* __restrict__ Alog,
                         float* __restrict__ dec, float* __restrict__ snd) {
    int c = blockIdx.x, b = blockIdx.y, d = threadIdx.x;
    __shared__ float Bsh[TC * DS];
    for (int idx = d; idx < TC * DS; idx += 256) {
        int t = idx >> 4, s = idx & 15;
        Bsh[idx] = dbc[(size_t)(b * L_ + c * TC + t) * 40 + 8 + s];
    }
    float Ar[DS];
#pragma unroll
    for (int s = 0; s < DS; s++) Ar[s] = -__expf(Alog[d * DS + s]);
    __syncthreads();
    float h[DS], cum[DS];
#pragma unroll
    for (int s = 0; s < DS; s++) { h[s] = 0.0f; cum[s] = 1.0f; }
    int rb = b * L_ + c * TC;
    for (int t = 0; t < TC; t++) {
        float dtv = dt[(size_t)(rb + t) * DI + d];
        float uv  = u2[(size_t)(rb + t) * DI + d];
        float xv = dtv * uv;
#pragma unroll
        for (int s = 0; s < DS; s++) {
            float dA = __expf(dtv * Ar[s]);
            h[s] = h[s] * dA + xv * Bsh[t * DS + s];
            cum[s] *= dA;
        }
    }
    size_t base = ((size_t)((b * NCH + c) * DI) + d) * DS;
#pragma unroll
    for (int s = 0; s < DS; s++) { snd[base + s] = h[s]; dec[base + s] = cum[s]; }
}

// ---------------- scan phase 2: sequential combine across chunks -----------------
__global__ void scan_ph2(const float* __restrict__ dec, const float* __restrict__ snd,
                         float* __restrict__ hin) {
    int b = blockIdx.x;
    int t = blockIdx.y * blockDim.x + threadIdx.x;   // 0..4095 = d*16+s
    float h = 0.0f;
    for (int c = 0; c < NCH; c++) {
        size_t idx = (size_t)(b * NCH + c) * (DI * DS) + t;
        hin[idx] = h;
        h = h * dec[idx] + snd[idx];
    }
}

// ---------------- scan phase 3: full scan with init state, emit y ----------------
__global__ void scan_ph3(const float* __restrict__ dt, const float* __restrict__ u2,
                         const float* __restrict__ dbc, const float* __restrict__ xz,
                         const float* __restrict__ Alog, const float* __restrict__ Dp,
                         const float* __restrict__ hin, float* __restrict__ yo) {
    int c = blockIdx.x, b = blockIdx.y, d = threadIdx.x;
    __shared__ float Bsh[TC * DS];
    __shared__ float Csh[TC * DS];
    for (int idx = d; idx < TC * DS; idx += 256) {
        int t = idx >> 4, s = idx & 15;
        size_t r = (size_t)(b * L_ + c * TC + t) * 40;
        Bsh[idx] = dbc[r + 8 + s];
        Csh[idx] = dbc[r + 24 + s];
    }
    float Ar[DS];
#pragma unroll
    for (int s = 0; s < DS; s++) Ar[s] = -__expf(Alog[d * DS + s]);
    size_t base = ((size_t)((b * NCH + c) * DI) + d) * DS;
    float h[DS];
#pragma unroll
    for (int s = 0; s < DS; s++) h[s] = hin[base + s];
    __syncthreads();
    float dpv = Dp[d];
    int rb = b * L_ + c * TC;
    for (int t = 0; t < TC; t++) {
        float dtv = dt[(size_t)(rb + t) * DI + d];
        float uv  = u2[(size_t)(rb + t) * DI + d];
        float xv = dtv * uv;
        float y = 0.0f;
#pragma unroll
        for (int s = 0; s < DS; s++) {
            float dA = __expf(dtv * Ar[s]);
            h[s] = h[s] * dA + xv * Bsh[t * DS + s];
            y += h[s] * Csh[t * DS + s];
        }
        float zv = xz[(size_t)(rb + t) * 512 + 256 + d];
        float sig = 1.0f / (1.0f + __expf(-zv));
        yo[(size_t)(rb + t) * DI + d] = (y + uv * dpv) * (zv * sig);
    }
}

// ---------------- final mean over L ----------------------------------------------
__global__ void zero_hg_kernel(float* __restrict__ hg) {
    int i = blockIdx.x * blockDim.x + threadIdx.x;
    if (i < B_ * DM) hg[i] = 0.0f;
}
__global__ void mean_kernel(const float* __restrict__ h, float* __restrict__ hg) {
    int b = blockIdx.x, chunk = blockIdx.y, d = threadIdx.x;
    float acc = 0.0f;
    int base = b * L_ + chunk * 256;
    for (int t = 0; t < 256; t++)
        acc += h[(size_t)(base + t) * DM + d];
    atomicAdd(&hg[b * DM + d], acc * (1.0f / L_));
}

// ---------------- host driver ----------------------------------------------------
extern "C" void kernel_launch(void* const* d_in, const int* in_sizes, int n_in,
                              void* d_out, int out_size) {
    const float* x       = (const float*)d_in[0];
    const float* proj_w  = (const float*)d_in[1];
    const float* proj_b  = (const float*)d_in[2];
    const float* ln_w    = (const float*)d_in[3];
    const float* ln_b    = (const float*)d_in[4];
    const float* in_w    = (const float*)d_in[5];
    const float* conv_w  = (const float*)d_in[6];
    const float* conv_b  = (const float*)d_in[7];
    const float* xproj_w = (const float*)d_in[8];
    const float* dt_w    = (const float*)d_in[9];
    const float* dt_b    = (const float*)d_in[10];
    const float* A_log   = (const float*)d_in[11];
    const float* Dp      = (const float*)d_in[12];
    const float* out_w   = (const float*)d_in[13];
    const float* lnout_w = (const float*)d_in[14];
    const float* lnout_b = (const float*)d_in[15];

    float* h  = (float*)d_out;                       // [B,L,128]
    float* hg = h + (size_t)NROWS * DM;              // [B,128]

    float *xn, *xz, *u2, *dbc, *dtb_, *yb, *dec, *snd, *hin;
    cudaGetSymbolAddress((void**)&xn,   g_xn);
    cudaGetSymbolAddress((void**)&xz,   g_xz);
    cudaGetSymbolAddress((void**)&u2,   g_u2);
    cudaGetSymbolAddress((void**)&dbc,  g_dbc);
    cudaGetSymbolAddress((void**)&dtb_, g_dt);
    cudaGetSymbolAddress((void**)&yb,   g_y);
    cudaGetSymbolAddress((void**)&dec,  g_dec);
    cudaGetSymbolAddress((void**)&snd,  g_snd);
    cudaGetSymbolAddress((void**)&hin,  g_hin);

    init_h_kernel<<<(NROWS * DM + 255) / 256, 256>>>(x, proj_w, proj_b, h);

    for (int i = 0; i < 4; i++) {
        ln_kernel<<<NROWS / 8, 256>>>(h, ln_w + i * DM, ln_b + i * DM, xn, NROWS);
        gemm_kernel<0><<<dim3(512 / GBN, NROWS / GBM), 256>>>(
            xn, in_w + (size_t)i * 512 * DM, xz, NROWS, 512, DM);
        conv_silu_kernel<<<(NROWS * DI + 255) / 256, 256>>>(
            xz, conv_w + i * DI * 4, conv_b + i * DI, u2);
        gemm_kernel<0><<<dim3(1, NROWS / GBM), 256>>>(
            u2, xproj_w + (size_t)i * 40 * DI, dbc, NROWS, 40, DI);
        dt_kernel<<<NROWS / 8, 256>>>(dbc, dt_w + i * DI * DTR, dt_b + i * DI, dtb_);
        scan_ph1<<<dim3(NCH, B_), 256>>>(dtb_, u2, dbc, A_log + i * DI * DS, dec, snd);
        scan_ph2<<<dim3(B_, (DI * DS) / 256), 256>>>(dec, snd, hin);
        scan_ph3<<<dim3(NCH, B_), 256>>>(dtb_, u2, dbc, xz, A_log + i * DI * DS,
                                         Dp + i * DI, hin, yb);
        gemm_kernel<1><<<dim3(1, NROWS / GBM), 256>>>(
            yb, out_w + (size_t)i * DM * DI, h, NROWS, DM, DI);
    }

    ln_kernel<<<NROWS / 8, 256>>>(h, lnout_w, lnout_b, h, NROWS);
    zero_hg_kernel<<<(B_ * DM + 255) / 256, 256>>>(hg);
    mean_kernel<<<dim3(B_, L_ / 256), 128>>>(h, hg);
}

// round 3
// speedup vs baseline: 2.1846x; 2.1846x over previous
#include <cuda_runtime.h>
#include <math.h>

#define B_    8
#define L_    8192
#define DM    128
#define DI    256
#define DS    16
#define DTR   8
#define NROWS (B_*L_)          // 65536
#define TC    64               // scan chunk length
#define NCH   (L_/TC)          // 128 chunks

// ---------------- scratch (device globals; no allocation allowed) ----------------
__device__ float g_xn [(size_t)NROWS*DM];     // layernorm output
__device__ float g_xz [(size_t)NROWS*512];    // in_proj output (u|z)
__device__ float g_u2 [(size_t)NROWS*DI];     // conv+silu output
__device__ float g_dbc[(size_t)NROWS*40];     // x_proj output (dt|B|C)
__device__ float g_y  [(size_t)NROWS*DI];     // scan output
__device__ float g_dec[B_*NCH*DI*DS];         // chunk decay products
__device__ float g_snd[B_*NCH*DI*DS];         // chunk end states
__device__ float g_hin[B_*NCH*DI*DS];         // chunk init states

// ---------------- init: h[b,l,d] = sum_c x[b,c,l]*proj_w[d,c] + proj_b[d] --------
__global__ void init_h_kernel(const float* __restrict__ x, const float* __restrict__ pw,
                              const float* __restrict__ pb, float* __restrict__ h) {
    int idx = blockIdx.x * blockDim.x + threadIdx.x;
    if (idx >= NROWS * DM) return;
    int d = idx & (DM - 1);
    int row = idx >> 7;
    int b = row >> 13;
    int l = row & (L_ - 1);
    float acc = pb[d];
#pragma unroll
    for (int c = 0; c < 3; c++)
        acc += x[(b * 3 + c) * L_ + l] * pw[d * 3 + c];
    h[idx] = acc;
}

// ---------------- layernorm: warp per row of 128 ---------------------------------
__global__ void ln_kernel(const float* __restrict__ in, const float* __restrict__ w,
                          const float* __restrict__ bias, float* __restrict__ out,
                          int nrows) {
    int gwarp = (blockIdx.x * blockDim.x + threadIdx.x) >> 5;
    int lane  = threadIdx.x & 31;
    if (gwarp >= nrows) return;
    const float4 v = *reinterpret_cast<const float4*>(&in[(size_t)gwarp * DM + lane * 4]);
    float s = v.x + v.y + v.z + v.w;
#pragma unroll
    for (int o = 16; o; o >>= 1) s += __shfl_xor_sync(0xffffffffu, s, o);
    float mu = s * (1.0f / DM);
    float d0 = v.x - mu, d1 = v.y - mu, d2 = v.z - mu, d3 = v.w - mu;
    float q = d0 * d0 + d1 * d1 + d2 * d2 + d3 * d3;
#pragma unroll
    for (int o = 16; o; o >>= 1) q += __shfl_xor_sync(0xffffffffu, q, o);
    float r = rsqrtf(q * (1.0f / DM) + 1e-5f);
    const float4 wv = *reinterpret_cast<const float4*>(&w[lane * 4]);
    const float4 bv = *reinterpret_cast<const float4*>(&bias[lane * 4]);
    float4 o4;
    o4.x = d0 * r * wv.x + bv.x;
    o4.y = d1 * r * wv.y + bv.y;
    o4.z = d2 * r * wv.z + bv.z;
    o4.w = d3 * r * wv.w + bv.w;
    *reinterpret_cast<float4*>(&out[(size_t)gwarp * DM + lane * 4]) = o4;
}

// ---------------- TF32 tensor-core GEMM: C[M,N] = A[M,K] * W[N,K]^T --------------
// Block tile 128x128, K tile 32. 256 threads = 8 warps (2 M x 4 N), warp 64x32.
// mma.sync.m16n8k8 tf32. EPI=1: C += result.
#define TBM 128
#define TBN 128
#define TBK 32
#define SPITCH (TBM + 4)

__device__ __forceinline__ unsigned f2tf(float x) {
    unsigned r;
    asm("cvt.rna.tf32.f32 %0, %1;" : "=r"(r) : "f"(x));
    return r;
}

template <int EPI>
__global__ __launch_bounds__(256) void gemm_tf32(
    const float* __restrict__ A, const float* __restrict__ W,
    float* __restrict__ C, int M, int N, int K) {
    __shared__ unsigned As[TBK * SPITCH];
    __shared__ unsigned Ws[TBK * SPITCH];
    int tid  = threadIdx.x;
    int warp = tid >> 5;
    int lane = tid & 31;
    int gid  = lane >> 2;      // groupID
    int tig  = lane & 3;       // thread-in-group
    int wm = (warp >> 2) * 64; // 0 or 64
    int wn = (warp & 3) * 32;  // 0,32,64,96
    int m0 = blockIdx.y * TBM;
    int n0 = blockIdx.x * TBN;

    float acc[4][4][4];
#pragma unroll
    for (int i = 0; i < 4; i++)
#pragma unroll
        for (int j = 0; j < 4; j++)
#pragma unroll
            for (int r = 0; r < 4; r++) acc[i][j][r] = 0.0f;

    for (int k0 = 0; k0 < K; k0 += TBK) {
        // load A tile: 128 rows x 32 k as float4 (8 float4 per row)
#pragma unroll
        for (int r = 0; r < 4; r++) {
            int linear = tid + r * 256;          // 0..1023
            int m = linear >> 3;
            int kq = (linear & 7) * 4;
            float4 v = *reinterpret_cast<const float4*>(&A[(size_t)(m0 + m) * K + k0 + kq]);
            As[(kq + 0) * SPITCH + m] = f2tf(v.x);
            As[(kq + 1) * SPITCH + m] = f2tf(v.y);
            As[(kq + 2) * SPITCH + m] = f2tf(v.z);
            As[(kq + 3) * SPITCH + m] = f2tf(v.w);
        }
#pragma unroll
        for (int r = 0; r < 4; r++) {
            int linear = tid + r * 256;
            int n = linear >> 3;
            int kq = (linear & 7) * 4;
            float4 v = make_float4(0.f, 0.f, 0.f, 0.f);
            if (n0 + n < N)
                v = *reinterpret_cast<const float4*>(&W[(size_t)(n0 + n) * K + k0 + kq]);
            Ws[(kq + 0) * SPITCH + n] = f2tf(v.x);
            Ws[(kq + 1) * SPITCH + n] = f2tf(v.y);
            Ws[(kq + 2) * SPITCH + n] = f2tf(v.z);
            Ws[(kq + 3) * SPITCH + n] = f2tf(v.w);
        }
        __syncthreads();
#pragma unroll
        for (int kk = 0; kk < 4; kk++) {        // 4 k-steps of 8
            unsigned a[4][4], bfr[4][2];
#pragma unroll
            for (int mf = 0; mf < 4; mf++) {
                int rb = wm + mf * 16;
                a[mf][0] = As[(kk * 8 + tig) * SPITCH + rb + gid];
                a[mf][1] = As[(kk * 8 + tig) * SPITCH + rb + gid + 8];
                a[mf][2] = As[(kk * 8 + tig + 4) * SPITCH + rb + gid];
                a[mf][3] = As[(kk * 8 + tig + 4) * SPITCH + rb + gid + 8];
            }
#pragma unroll
            for (int nf = 0; nf < 4; nf++) {
                int nb = wn + nf * 8 + gid;
                bfr[nf][0] = Ws[(kk * 8 + tig) * SPITCH + nb];
                bfr[nf][1] = Ws[(kk * 8 + tig + 4) * SPITCH + nb];
            }
#pragma unroll
            for (int mf = 0; mf < 4; mf++)
#pragma unroll
                for (int nf = 0; nf < 4; nf++) {
                    asm volatile(
                        "mma.sync.aligned.m16n8k8.row.col.f32.tf32.tf32.f32 "
                        "{%0,%1,%2,%3}, {%4,%5,%6,%7}, {%8,%9}, {%0,%1,%2,%3};"
                        : "+f"(acc[mf][nf][0]), "+f"(acc[mf][nf][1]),
                          "+f"(acc[mf][nf][2]), "+f"(acc[mf][nf][3])
                        : "r"(a[mf][0]), "r"(a[mf][1]), "r"(a[mf][2]), "r"(a[mf][3]),
                          "r"(bfr[nf][0]), "r"(bfr[nf][1]));
                }
        }
        __syncthreads();
    }

    // epilogue
#pragma unroll
    for (int mf = 0; mf < 4; mf++) {
        int row0 = m0 + wm + mf * 16 + gid;
#pragma unroll
        for (int nf = 0; nf < 4; nf++) {
            int col = n0 + wn + nf * 8 + tig * 2;
            if (col < N) {
                size_t o0 = (size_t)row0 * N + col;
                size_t o1 = (size_t)(row0 + 8) * N + col;
                if (EPI == 1) {
                    C[o0]     += acc[mf][nf][0];
                    C[o0 + 1] += acc[mf][nf][1];
                    C[o1]     += acc[mf][nf][2];
                    C[o1 + 1] += acc[mf][nf][3];
                } else {
                    C[o0]     = acc[mf][nf][0];
                    C[o0 + 1] = acc[mf][nf][1];
                    C[o1]     = acc[mf][nf][2];
                    C[o1 + 1] = acc[mf][nf][3];
                }
            }
        }
    }
}

// ---------------- causal depthwise conv1d (kernel 4) + silu, float4 --------------
__global__ void conv_silu_kernel(const float* __restrict__ xz, const float* __restrict__ cw,
                                 const float* __restrict__ cb, float* __restrict__ u2) {
    int idx = blockIdx.x * blockDim.x + threadIdx.x;   // NROWS * 64
    if (idx >= NROWS * 64) return;
    int d4  = idx & 63;          // group of 4 channels
    int row = idx >> 6;
    int l   = row & (L_ - 1);
    const float4* cw4 = reinterpret_cast<const float4*>(cw);
    float4 t0 = cw4[d4 * 4 + 0];   // taps of channel 4*d4+0
    float4 t1 = cw4[d4 * 4 + 1];
    float4 t2 = cw4[d4 * 4 + 2];
    float4 t3 = cw4[d4 * 4 + 3];
    float wA[4] = {t0.x, t0.y, t0.z, t0.w};
    float wB[4] = {t1.x, t1.y, t1.z, t1.w};
    float wC[4] = {t2.x, t2.y, t2.z, t2.w};
    float wD[4] = {t3.x, t3.y, t3.z, t3.w};
    float4 acc = reinterpret_cast<const float4*>(cb)[d4];
#pragma unroll
    for (int k = 0; k < 4; k++) {
        int lk = l - 3 + k;
        if (lk >= 0) {
            float4 v = reinterpret_cast<const float4*>(xz)[(size_t)(row - 3 + k) * 128 + d4];
            acc.x += v.x * wA[k];
            acc.y += v.y * wB[k];
            acc.z += v.z * wC[k];
            acc.w += v.w * wD[k];
        }
    }
    float4 o;
    o.x = acc.x / (1.0f + __expf(-acc.x));
    o.y = acc.y / (1.0f + __expf(-acc.y));
    o.z = acc.z / (1.0f + __expf(-acc.z));
    o.w = acc.w / (1.0f + __expf(-acc.w));
    reinterpret_cast<float4*>(u2)[idx] = o;
}

// ---------------- scan phase 1: per-chunk local scan (init=0), dt fused ----------
__global__ void scan_ph1(const float* __restrict__ u2, const float* __restrict__ dbc,
                         const float* __restrict__ Alog,
                         const float* __restrict__ dtw, const float* __restrict__ dtb,
                         float* __restrict__ dec, float* __restrict__ snd) {
    int c = blockIdx.x, b = blockIdx.y, d = threadIdx.x;
    __shared__ float Bsh[TC * DS];
    __shared__ float Dsh[TC * DTR];
    int rb = b * L_ + c * TC;
    for (int idx = d; idx < TC * 24; idx += 256) {
        int t = idx / 24, f = idx % 24;
        float v = dbc[(size_t)(rb + t) * 40 + f];
        if (f < 8) Dsh[t * 8 + f] = v;
        else       Bsh[t * 16 + f - 8] = v;
    }
    float wreg[DTR];
#pragma unroll
    for (int k = 0; k < DTR; k++) wreg[k] = dtw[d * DTR + k];
    float breg = dtb[d];
    float Ar[DS];
#pragma unroll
    for (int s = 0; s < DS; s++) Ar[s] = -__expf(Alog[d * DS + s]);
    __syncthreads();
    float h[DS], cum[DS];
#pragma unroll
    for (int s = 0; s < DS; s++) { h[s] = 0.0f; cum[s] = 1.0f; }
    for (int t = 0; t < TC; t++) {
        float draw = breg;
#pragma unroll
        for (int k = 0; k < DTR; k++) draw += Dsh[t * 8 + k] * wreg[k];
        float dtv = (draw > 20.0f) ? draw : log1pf(__expf(draw));
        float uv  = u2[(size_t)(rb + t) * DI + d];
        float xv = dtv * uv;
#pragma unroll
        for (int s = 0; s < DS; s++) {
            float dA = __expf(dtv * Ar[s]);
            h[s] = h[s] * dA + xv * Bsh[t * DS + s];
            cum[s] *= dA;
        }
    }
    size_t base = ((size_t)((b * NCH + c) * DI) + d) * DS;
#pragma unroll
    for (int s = 0; s < DS; s++) { snd[base + s] = h[s]; dec[base + s] = cum[s]; }
}

// ---------------- scan phase 2: sequential combine across chunks -----------------
__global__ void scan_ph2(const float* __restrict__ dec, const float* __restrict__ snd,
                         float* __restrict__ hin) {
    int b = blockIdx.x;
    int t = blockIdx.y * blockDim.x + threadIdx.x;
    float h = 0.0f;
    for (int c = 0; c < NCH; c++) {
        size_t idx = (size_t)(b * NCH + c) * (DI * DS) + t;
        hin[idx] = h;
        h = h * dec[idx] + snd[idx];
    }
}

// ---------------- scan phase 3: full scan with init state, emit y ----------------
__global__ void scan_ph3(const float* __restrict__ u2, const float* __restrict__ dbc,
                         const float* __restrict__ xz, const float* __restrict__ Alog,
                         const float* __restrict__ dtw, const float* __restrict__ dtb,
                         const float* __restrict__ Dp, const float* __restrict__ hin,
                         float* __restrict__ yo) {
    int c = blockIdx.x, b = blockIdx.y, d = threadIdx.x;
    __shared__ float Bsh[TC * DS];
    __shared__ float Csh[TC * DS];
    __shared__ float Dsh[TC * DTR];
    int rb = b * L_ + c * TC;
    for (int idx = d; idx < TC * 40; idx += 256) {
        int t = idx / 40, f = idx % 40;
        float v = dbc[(size_t)(rb + t) * 40 + f];
        if (f < 8)       Dsh[t * 8 + f] = v;
        else if (f < 24) Bsh[t * 16 + f - 8] = v;
        else             Csh[t * 16 + f - 24] = v;
    }
    float wreg[DTR];
#pragma unroll
    for (int k = 0; k < DTR; k++) wreg[k] = dtw[d * DTR + k];
    float breg = dtb[d];
    float Ar[DS];
#pragma unroll
    for (int s = 0; s < DS; s++) Ar[s] = -__expf(Alog[d * DS + s]);
    size_t base = ((size_t)((b * NCH + c) * DI) + d) * DS;
    float h[DS];
#pragma unroll
    for (int s = 0; s < DS; s++) h[s] = hin[base + s];
    __syncthreads();
    float dpv = Dp[d];
    for (int t = 0; t < TC; t++) {
        float draw = breg;
#pragma unroll
        for (int k = 0; k < DTR; k++) draw += Dsh[t * 8 + k] * wreg[k];
        float dtv = (draw > 20.0f) ? draw : log1pf(__expf(draw));
        float uv  = u2[(size_t)(rb + t) * DI + d];
        float xv = dtv * uv;
        float y = 0.0f;
#pragma unroll
        for (int s = 0; s < DS; s++) {
            float dA = __expf(dtv * Ar[s]);
            h[s] = h[s] * dA + xv * Bsh[t * DS + s];
            y += h[s] * Csh[t * DS + s];
        }
        float zv = xz[(size_t)(rb + t) * 512 + 256 + d];
        float sig = 1.0f / (1.0f + __expf(-zv));
        yo[(size_t)(rb + t) * DI + d] = (y + uv * dpv) * (zv * sig);
    }
}

// ---------------- final mean over L ----------------------------------------------
__global__ void zero_hg_kernel(float* __restrict__ hg) {
    int i = blockIdx.x * blockDim.x + threadIdx.x;
    if (i < B_ * DM) hg[i] = 0.0f;
}
__global__ void mean_kernel(const float* __restrict__ h, float* __restrict__ hg) {
    int b = blockIdx.x, chunk = blockIdx.y, d = threadIdx.x;
    float acc = 0.0f;
    int base = b * L_ + chunk * 256;
    for (int t = 0; t < 256; t++)
        acc += h[(size_t)(base + t) * DM + d];
    atomicAdd(&hg[b * DM + d], acc * (1.0f / L_));
}

// ---------------- host driver ----------------------------------------------------
extern "C" void kernel_launch(void* const* d_in, const int* in_sizes, int n_in,
                              void* d_out, int out_size) {
    const float* x       = (const float*)d_in[0];
    const float* proj_w  = (const float*)d_in[1];
    const float* proj_b  = (const float*)d_in[2];
    const float* ln_w    = (const float*)d_in[3];
    const float* ln_b    = (const float*)d_in[4];
    const float* in_w    = (const float*)d_in[5];
    const float* conv_w  = (const float*)d_in[6];
    const float* conv_b  = (const float*)d_in[7];
    const float* xproj_w = (const float*)d_in[8];
    const float* dt_w    = (const float*)d_in[9];
    const float* dt_b    = (const float*)d_in[10];
    const float* A_log   = (const float*)d_in[11];
    const float* Dp      = (const float*)d_in[12];
    const float* out_w   = (const float*)d_in[13];
    const float* lnout_w = (const float*)d_in[14];
    const float* lnout_b = (const float*)d_in[15];

    float* h  = (float*)d_out;                       // [B,L,128]
    float* hg = h + (size_t)NROWS * DM;              // [B,128]

    float *xn, *xz, *u2, *dbc, *yb, *dec, *snd, *hin;
    cudaGetSymbolAddress((void**)&xn,  g_xn);
    cudaGetSymbolAddress((void**)&xz,  g_xz);
    cudaGetSymbolAddress((void**)&u2,  g_u2);
    cudaGetSymbolAddress((void**)&dbc, g_dbc);
    cudaGetSymbolAddress((void**)&yb,  g_y);
    cudaGetSymbolAddress((void**)&dec, g_dec);
    cudaGetSymbolAddress((void**)&snd, g_snd);
    cudaGetSymbolAddress((void**)&hin, g_hin);

    init_h_kernel<<<(NROWS * DM + 255) / 256, 256>>>(x, proj_w, proj_b, h);

    for (int i = 0; i < 4; i++) {
        ln_kernel<<<NROWS / 8, 256>>>(h, ln_w + i * DM, ln_b + i * DM, xn, NROWS);
        gemm_tf32<0><<<dim3(4, NROWS / TBM), 256>>>(
            xn, in_w + (size_t)i * 512 * DM, xz, NROWS, 512, DM);
        conv_silu_kernel<<<(NROWS * 64 + 255) / 256, 256>>>(
            xz, conv_w + i * DI * 4, conv_b + i * DI, u2);
        gemm_tf32<0><<<dim3(1, NROWS / TBM), 256>>>(
            u2, xproj_w + (size_t)i * 40 * DI, dbc, NROWS, 40, DI);
        scan_ph1<<<dim3(NCH, B_), 256>>>(u2, dbc, A_log + i * DI * DS,
                                         dt_w + i * DI * DTR, dt_b + i * DI, dec, snd);
        scan_ph2<<<dim3(B_, (DI * DS) / 256), 256>>>(dec, snd, hin);
        scan_ph3<<<dim3(NCH, B_), 256>>>(u2, dbc, xz, A_log + i * DI * DS,
                                         dt_w + i * DI * DTR, dt_b + i * DI,
                                         Dp + i * DI, hin, yb);
        gemm_tf32<1><<<dim3(1, NROWS / TBM), 256>>>(
            yb, out_w + (size_t)i * DM * DI, h, NROWS, DM, DI);
    }

    ln_kernel<<<NROWS / 8, 256>>>(h, lnout_w, lnout_b, h, NROWS);
    zero_hg_kernel<<<(B_ * DM + 255) / 256, 256>>>(hg);
    mean_kernel<<<dim3(B_, L_ / 256), 128>>>(h, hg);
}

// round 4
// speedup vs baseline: 2.1922x; 1.0035x over previous
#include <cuda_runtime.h>
#include <math.h>

#define B_    8
#define L_    8192
#define DM    128
#define DI    256
#define DS    16
#define DTR   8
#define NROWS (B_*L_)          // 65536
#define TC    64               // scan chunk length
#define NCH   (L_/TC)          // 128 chunks

// ---------------- scratch (device globals; no allocation allowed) ----------------
__device__ float g_xn [(size_t)NROWS*DM];     // layernorm output
__device__ float g_xz [(size_t)NROWS*512];    // in_proj output (u|z)
__device__ float g_u2 [(size_t)NROWS*DI];     // conv+silu output
__device__ float g_dbc[(size_t)NROWS*40];     // x_proj output (dt|B|C)
__device__ float g_y  [(size_t)NROWS*DI];     // scan output
__device__ float g_dec[B_*NCH*DI*DS];         // chunk decay products
__device__ float g_snd[B_*NCH*DI*DS];         // chunk end states
__device__ float g_hin[B_*NCH*DI*DS];         // chunk init states

// ---------------- init: h[b,l,d] = sum_c x[b,c,l]*proj_w[d,c] + proj_b[d] --------
__global__ void init_h_kernel(const float* __restrict__ x, const float* __restrict__ pw,
                              const float* __restrict__ pb, float* __restrict__ h) {
    int idx = blockIdx.x * blockDim.x + threadIdx.x;
    if (idx >= NROWS * DM) return;
    int d = idx & (DM - 1);
    int row = idx >> 7;
    int b = row >> 13;
    int l = row & (L_ - 1);
    float acc = pb[d];
#pragma unroll
    for (int c = 0; c < 3; c++)
        acc += x[(b * 3 + c) * L_ + l] * pw[d * 3 + c];
    h[idx] = acc;
}

// ---------------- layernorm: warp per row of 128 (only used once, layer 0) -------
__global__ void ln_kernel(const float* __restrict__ in, const float* __restrict__ w,
                          const float* __restrict__ bias, float* __restrict__ out,
                          int nrows) {
    int gwarp = (blockIdx.x * blockDim.x + threadIdx.x) >> 5;
    int lane  = threadIdx.x & 31;
    if (gwarp >= nrows) return;
    const float4 v = *reinterpret_cast<const float4*>(&in[(size_t)gwarp * DM + lane * 4]);
    float s = v.x + v.y + v.z + v.w;
#pragma unroll
    for (int o = 16; o; o >>= 1) s += __shfl_xor_sync(0xffffffffu, s, o);
    float mu = s * (1.0f / DM);
    float d0 = v.x - mu, d1 = v.y - mu, d2 = v.z - mu, d3 = v.w - mu;
    float q = d0 * d0 + d1 * d1 + d2 * d2 + d3 * d3;
#pragma unroll
    for (int o = 16; o; o >>= 1) q += __shfl_xor_sync(0xffffffffu, q, o);
    float r = rsqrtf(q * (1.0f / DM) + 1e-5f);
    const float4 wv = *reinterpret_cast<const float4*>(&w[lane * 4]);
    const float4 bv = *reinterpret_cast<const float4*>(&bias[lane * 4]);
    float4 o4;
    o4.x = d0 * r * wv.x + bv.x;
    o4.y = d1 * r * wv.y + bv.y;
    o4.z = d2 * r * wv.z + bv.z;
    o4.w = d3 * r * wv.w + bv.w;
    *reinterpret_cast<float4*>(&out[(size_t)gwarp * DM + lane * 4]) = o4;
}

// ---------------- TF32 tensor-core GEMM: C[M,N] = A[M,K] * W[N,K]^T --------------
#define TBM 128
#define TBN 128
#define TBK 32
#define SPITCH (TBM + 4)

__device__ __forceinline__ unsigned f2tf(float x) {
    unsigned r;
    asm("cvt.rna.tf32.f32 %0, %1;" : "=r"(r) : "f"(x));
    return r;
}

// shared mainloop body: accumulates block tile into acc
__device__ __forceinline__ void gemm_mainloop(
    const float* __restrict__ A, const float* __restrict__ W,
    int M, int N, int K, int m0, int n0,
    unsigned* As, unsigned* Ws, float acc[4][4][4]) {
    int tid  = threadIdx.x;
    int warp = tid >> 5;
    int lane = tid & 31;
    int gid  = lane >> 2;
    int tig  = lane & 3;
    int wm = (warp >> 2) * 64;
    int wn = (warp & 3) * 32;

    for (int k0 = 0; k0 < K; k0 += TBK) {
#pragma unroll
        for (int r = 0; r < 4; r++) {
            int linear = tid + r * 256;
            int m = linear >> 3;
            int kq = (linear & 7) * 4;
            float4 v = *reinterpret_cast<const float4*>(&A[(size_t)(m0 + m) * K + k0 + kq]);
            As[(kq + 0) * SPITCH + m] = f2tf(v.x);
            As[(kq + 1) * SPITCH + m] = f2tf(v.y);
            As[(kq + 2) * SPITCH + m] = f2tf(v.z);
            As[(kq + 3) * SPITCH + m] = f2tf(v.w);
        }
#pragma unroll
        for (int r = 0; r < 4; r++) {
            int linear = tid + r * 256;
            int n = linear >> 3;
            int kq = (linear & 7) * 4;
            float4 v = make_float4(0.f, 0.f, 0.f, 0.f);
            if (n0 + n < N)
                v = *reinterpret_cast<const float4*>(&W[(size_t)(n0 + n) * K + k0 + kq]);
            Ws[(kq + 0) * SPITCH + n] = f2tf(v.x);
            Ws[(kq + 1) * SPITCH + n] = f2tf(v.y);
            Ws[(kq + 2) * SPITCH + n] = f2tf(v.z);
            Ws[(kq + 3) * SPITCH + n] = f2tf(v.w);
        }
        __syncthreads();
#pragma unroll
        for (int kk = 0; kk < 4; kk++) {
            unsigned a[4][4], bfr[4][2];
#pragma unroll
            for (int mf = 0; mf < 4; mf++) {
                int rb = wm + mf * 16;
                a[mf][0] = As[(kk * 8 + tig) * SPITCH + rb + gid];
                a[mf][1] = As[(kk * 8 + tig) * SPITCH + rb + gid + 8];
                a[mf][2] = As[(kk * 8 + tig + 4) * SPITCH + rb + gid];
                a[mf][3] = As[(kk * 8 + tig + 4) * SPITCH + rb + gid + 8];
            }
#pragma unroll
            for (int nf = 0; nf < 4; nf++) {
                int nb = wn + nf * 8 + gid;
                bfr[nf][0] = Ws[(kk * 8 + tig) * SPITCH + nb];
                bfr[nf][1] = Ws[(kk * 8 + tig + 4) * SPITCH + nb];
            }
#pragma unroll
            for (int mf = 0; mf < 4; mf++)
#pragma unroll
                for (int nf = 0; nf < 4; nf++) {
                    asm volatile(
                        "mma.sync.aligned.m16n8k8.row.col.f32.tf32.tf32.f32 "
                        "{%0,%1,%2,%3}, {%4,%5,%6,%7}, {%8,%9}, {%0,%1,%2,%3};"
                        : "+f"(acc[mf][nf][0]), "+f"(acc[mf][nf][1]),
                          "+f"(acc[mf][nf][2]), "+f"(acc[mf][nf][3])
                        : "r"(a[mf][0]), "r"(a[mf][1]), "r"(a[mf][2]), "r"(a[mf][3]),
                          "r"(bfr[nf][0]), "r"(bfr[nf][1]));
                }
        }
        __syncthreads();
    }
}

__global__ __launch_bounds__(256) void gemm_tf32(
    const float* __restrict__ A, const float* __restrict__ W,
    float* __restrict__ C, int M, int N, int K) {
    __shared__ unsigned As[TBK * SPITCH];
    __shared__ unsigned Ws[TBK * SPITCH];
    int tid  = threadIdx.x;
    int warp = tid >> 5;
    int lane = tid & 31;
    int gid  = lane >> 2;
    int tig  = lane & 3;
    int wm = (warp >> 2) * 64;
    int wn = (warp & 3) * 32;
    int m0 = blockIdx.y * TBM;
    int n0 = blockIdx.x * TBN;

    float acc[4][4][4];
#pragma unroll
    for (int i = 0; i < 4; i++)
#pragma unroll
        for (int j = 0; j < 4; j++)
#pragma unroll
            for (int r = 0; r < 4; r++) acc[i][j][r] = 0.0f;

    gemm_mainloop(A, W, M, N, K, m0, n0, As, Ws, acc);

#pragma unroll
    for (int mf = 0; mf < 4; mf++) {
        int row0 = m0 + wm + mf * 16 + gid;
#pragma unroll
        for (int nf = 0; nf < 4; nf++) {
            int col = n0 + wn + nf * 8 + tig * 2;
            if (col < N) {
                size_t o0 = (size_t)row0 * N + col;
                size_t o1 = (size_t)(row0 + 8) * N + col;
                C[o0]     = acc[mf][nf][0];
                C[o0 + 1] = acc[mf][nf][1];
                C[o1]     = acc[mf][nf][2];
                C[o1 + 1] = acc[mf][nf][3];
            }
        }
    }
}

// ---------------- out-proj GEMM + residual + fused LayerNorm ---------------------
// N = DM = 128 (one tile) => block owns complete rows. Computes resid = h + A*W^T,
// writes resid to h (unless LAST), then LN(resid) -> xn (or h if LAST).
template <bool LAST>
__global__ __launch_bounds__(256) void gemm_out_fused(
    const float* __restrict__ A, const float* __restrict__ W,
    float* __restrict__ h, float* __restrict__ xn,
    const float* __restrict__ lnw, const float* __restrict__ lnb, int K) {
    __shared__ unsigned As[TBK * SPITCH];
    __shared__ unsigned Ws[TBK * SPITCH];
    __shared__ float red[2][128][4];
    int tid  = threadIdx.x;
    int warp = tid >> 5;
    int lane = tid & 31;
    int gid  = lane >> 2;
    int tig  = lane & 3;
    int wm = (warp >> 2) * 64;
    int wn = (warp & 3) * 32;
    int m0 = blockIdx.y * TBM;

    float acc[4][4][4];
#pragma unroll
    for (int i = 0; i < 4; i++)
#pragma unroll
        for (int j = 0; j < 4; j++)
#pragma unroll
            for (int r = 0; r < 4; r++) acc[i][j][r] = 0.0f;

    gemm_mainloop(A, W, 0, DM, K, m0, 0, As, Ws, acc);

    // residual add (acc becomes resid); write resid to h unless LAST
#pragma unroll
    for (int mf = 0; mf < 4; mf++) {
        int row0 = m0 + wm + mf * 16 + gid;
#pragma unroll
        for (int nf = 0; nf < 4; nf++) {
            int col = wn + nf * 8 + tig * 2;
            size_t o0 = (size_t)row0 * DM + col;
            size_t o1 = (size_t)(row0 + 8) * DM + col;
            acc[mf][nf][0] += h[o0];
            acc[mf][nf][1] += h[o0 + 1];
            acc[mf][nf][2] += h[o1];
            acc[mf][nf][3] += h[o1 + 1];
            if (!LAST) {
                h[o0]     = acc[mf][nf][0];
                h[o0 + 1] = acc[mf][nf][1];
                h[o1]     = acc[mf][nf][2];
                h[o1 + 1] = acc[mf][nf][3];
            }
        }
    }

    // per-row mean/var reduction: tig (shfl) then cross-warp (smem)
#pragma unroll
    for (int mf = 0; mf < 4; mf++) {
#pragma unroll
        for (int half = 0; half < 2; half++) {
            float s = 0.f, q = 0.f;
#pragma unroll
            for (int nf = 0; nf < 4; nf++) {
#pragma unroll
                for (int c = 0; c < 2; c++) {
                    float v = acc[mf][nf][half * 2 + c];
                    s += v; q += v * v;
                }
            }
            s += __shfl_xor_sync(0xffffffffu, s, 1);
            s += __shfl_xor_sync(0xffffffffu, s, 2);
            q += __shfl_xor_sync(0xffffffffu, q, 1);
            q += __shfl_xor_sync(0xffffffffu, q, 2);
            int row = wm + mf * 16 + gid + half * 8;   // local 0..127
            if (tig == 0) {
                red[0][row][warp & 3] = s;
                red[1][row][warp & 3] = q;
            }
        }
    }
    __syncthreads();

#pragma unroll
    for (int mf = 0; mf < 4; mf++) {
#pragma unroll
        for (int half = 0; half < 2; half++) {
            int row = wm + mf * 16 + gid + half * 8;
            float s = red[0][row][0] + red[0][row][1] + red[0][row][2] + red[0][row][3];
            float q = red[1][row][0] + red[1][row][1] + red[1][row][2] + red[1][row][3];
            float mu = s * (1.0f / DM);
            float var = q * (1.0f / DM) - mu * mu;
            float rsig = rsqrtf(var + 1e-5f);
            size_t rbase = (size_t)(m0 + row) * DM;
            float* dst = LAST ? h : xn;
#pragma unroll
            for (int nf = 0; nf < 4; nf++) {
#pragma unroll
                for (int c = 0; c < 2; c++) {
                    int col = wn + nf * 8 + tig * 2 + c;
                    float v = acc[mf][nf][half * 2 + c];
                    dst[rbase + col] = (v - mu) * rsig * lnw[col] + lnb[col];
                }
            }
        }
    }
}

// ---------------- causal depthwise conv1d + silu: 4 timesteps per thread ---------
__global__ void conv_silu_kernel(const float* __restrict__ xz, const float* __restrict__ cw,
                                 const float* __restrict__ cb, float* __restrict__ u2) {
    int idx = blockIdx.x * blockDim.x + threadIdx.x;   // (NROWS/4) * 64
    if (idx >= (NROWS / 4) * 64) return;
    int d4 = idx & 63;
    int g  = idx >> 6;
    int l0 = (g & (L_ / 4 - 1)) * 4;
    int b  = g >> 11;
    int row0 = b * L_ + l0;

    const float4* cw4 = reinterpret_cast<const float4*>(cw);
    float4 t0 = cw4[d4 * 4 + 0];
    float4 t1 = cw4[d4 * 4 + 1];
    float4 t2 = cw4[d4 * 4 + 2];
    float4 t3 = cw4[d4 * 4 + 3];
    float wA[4] = {t0.x, t0.y, t0.z, t0.w};
    float wB[4] = {t1.x, t1.y, t1.z, t1.w};
    float wC[4] = {t2.x, t2.y, t2.z, t2.w};
    float wD[4] = {t3.x, t3.y, t3.z, t3.w};
    float4 bias = reinterpret_cast<const float4*>(cb)[d4];

    float4 v[7];
#pragma unroll
    for (int k = 0; k < 7; k++) {
        if (l0 - 3 + k >= 0)
            v[k] = reinterpret_cast<const float4*>(xz)[(size_t)(row0 - 3 + k) * 128 + d4];
        else
            v[k] = make_float4(0.f, 0.f, 0.f, 0.f);
    }
#pragma unroll
    for (int j = 0; j < 4; j++) {
        float4 acc = bias;
#pragma unroll
        for (int k = 0; k < 4; k++) {
            float4 x = v[j + k];
            acc.x += x.x * wA[k];
            acc.y += x.y * wB[k];
            acc.z += x.z * wC[k];
            acc.w += x.w * wD[k];
        }
        float4 o;
        o.x = acc.x / (1.0f + __expf(-acc.x));
        o.y = acc.y / (1.0f + __expf(-acc.y));
        o.z = acc.z / (1.0f + __expf(-acc.z));
        o.w = acc.w / (1.0f + __expf(-acc.w));
        reinterpret_cast<float4*>(u2)[(size_t)(row0 + j) * 64 + d4] = o;
    }
}

// ---------------- softplus helper -------------------------------------------------
__device__ __forceinline__ float softplusf(float x) {
    return (x > 20.0f) ? x : log1pf(__expf(x));
}

// ---------------- scan phase 1: per-chunk local scan (init=0), dt fused ----------
__global__ void scan_ph1(const float* __restrict__ u2, const float* __restrict__ dbc,
                         const float* __restrict__ Alog,
                         const float* __restrict__ dtw, const float* __restrict__ dtb,
                         float* __restrict__ dec, float* __restrict__ snd) {
    int c = blockIdx.x, b = blockIdx.y, d = threadIdx.x;
    __shared__ float Bsh[TC * DS];
    __shared__ float Dsh[TC * DTR];
    int rb = b * L_ + c * TC;
    for (int idx = d; idx < TC * 24; idx += 256) {
        int t = idx / 24, f = idx % 24;
        float v = dbc[(size_t)(rb + t) * 40 + f];
        if (f < 8) Dsh[t * 8 + f] = v;
        else       Bsh[t * 16 + f - 8] = v;
    }
    float wreg[DTR];
#pragma unroll
    for (int k = 0; k < DTR; k++) wreg[k] = dtw[d * DTR + k];
    float breg = dtb[d];
    float Ar[DS];
    bool fast = true;
#pragma unroll
    for (int s = 0; s < DS; s++) {
        Ar[s] = -__expf(Alog[d * DS + s]);
        fast = fast && (fabsf(Ar[s] + (float)(s + 1)) < 1e-4f * (float)(s + 1));
    }
    __syncthreads();
    float h[DS], cum[DS];
#pragma unroll
    for (int s = 0; s < DS; s++) { h[s] = 0.0f; cum[s] = 1.0f; }
    float sdt = 0.0f;
    for (int t = 0; t < TC; t++) {
        float draw = breg;
#pragma unroll
        for (int k = 0; k < DTR; k++) draw += Dsh[t * 8 + k] * wreg[k];
        float dtv = softplusf(draw);
        float uv  = u2[(size_t)(rb + t) * DI + d];
        float xv = dtv * uv;
        if (fast) {
            float r = __expf(-dtv);
            float p = 1.0f;
            sdt += dtv;
#pragma unroll
            for (int s = 0; s < DS; s++) {
                p *= r;
                h[s] = h[s] * p + xv * Bsh[t * DS + s];
            }
        } else {
#pragma unroll
            for (int s = 0; s < DS; s++) {
                float dA = __expf(dtv * Ar[s]);
                h[s] = h[s] * dA + xv * Bsh[t * DS + s];
                cum[s] *= dA;
            }
        }
    }
    if (fast) {
        float R = __expf(-sdt);
        float p = 1.0f;
#pragma unroll
        for (int s = 0; s < DS; s++) { p *= R; cum[s] = p; }
    }
    size_t base = ((size_t)((b * NCH + c) * DI) + d) * DS;
#pragma unroll
    for (int s = 0; s < DS; s++) { snd[base + s] = h[s]; dec[base + s] = cum[s]; }
}

// ---------------- scan phase 2: sequential combine across chunks -----------------
__global__ void scan_ph2(const float* __restrict__ dec, const float* __restrict__ snd,
                         float* __restrict__ hin) {
    int b = blockIdx.x;
    int t = blockIdx.y * blockDim.x + threadIdx.x;
    float h = 0.0f;
    for (int c = 0; c < NCH; c++) {
        size_t idx = (size_t)(b * NCH + c) * (DI * DS) + t;
        hin[idx] = h;
        h = h * dec[idx] + snd[idx];
    }
}

// ---------------- scan phase 3: full scan with init state, emit y ----------------
__global__ void scan_ph3(const float* __restrict__ u2, const float* __restrict__ dbc,
                         const float* __restrict__ xz, const float* __restrict__ Alog,
                         const float* __restrict__ dtw, const float* __restrict__ dtb,
                         const float* __restrict__ Dp, const float* __restrict__ hin,
                         float* __restrict__ yo) {
    int c = blockIdx.x, b = blockIdx.y, d = threadIdx.x;
    __shared__ float Bsh[TC * DS];
    __shared__ float Csh[TC * DS];
    __shared__ float Dsh[TC * DTR];
    int rb = b * L_ + c * TC;
    for (int idx = d; idx < TC * 40; idx += 256) {
        int t = idx / 40, f = idx % 40;
        float v = dbc[(size_t)(rb + t) * 40 + f];
        if (f < 8)       Dsh[t * 8 + f] = v;
        else if (f < 24) Bsh[t * 16 + f - 8] = v;
        else             Csh[t * 16 + f - 24] = v;
    }
    float wreg[DTR];
#pragma unroll
    for (int k = 0; k < DTR; k++) wreg[k] = dtw[d * DTR + k];
    float breg = dtb[d];
    float Ar[DS];
    bool fast = true;
#pragma unroll
    for (int s = 0; s < DS; s++) {
        Ar[s] = -__expf(Alog[d * DS + s]);
        fast = fast && (fabsf(Ar[s] + (float)(s + 1)) < 1e-4f * (float)(s + 1));
    }
    size_t base = ((size_t)((b * NCH + c) * DI) + d) * DS;
    float h[DS];
#pragma unroll
    for (int s = 0; s < DS; s++) h[s] = hin[base + s];
    __syncthreads();
    float dpv = Dp[d];
    for (int t = 0; t < TC; t++) {
        float draw = breg;
#pragma unroll
        for (int k = 0; k < DTR; k++) draw += Dsh[t * 8 + k] * wreg[k];
        float dtv = softplusf(draw);
        float uv  = u2[(size_t)(rb + t) * DI + d];
        float xv = dtv * uv;
        float y = 0.0f;
        if (fast) {
            float r = __expf(-dtv);
            float p = 1.0f;
#pragma unroll
            for (int s = 0; s < DS; s++) {
                p *= r;
                h[s] = h[s] * p + xv * Bsh[t * DS + s];
                y += h[s] * Csh[t * DS + s];
            }
        } else {
#pragma unroll
            for (int s = 0; s < DS; s++) {
                float dA = __expf(dtv * Ar[s]);
                h[s] = h[s] * dA + xv * Bsh[t * DS + s];
                y += h[s] * Csh[t * DS + s];
            }
        }
        float zv = xz[(size_t)(rb + t) * 512 + 256 + d];
        float sig = 1.0f / (1.0f + __expf(-zv));
        yo[(size_t)(rb + t) * DI + d] = (y + uv * dpv) * (zv * sig);
    }
}

// ---------------- final mean over L ----------------------------------------------
__global__ void zero_hg_kernel(float* __restrict__ hg) {
    int i = blockIdx.x * blockDim.x + threadIdx.x;
    if (i < B_ * DM) hg[i] = 0.0f;
}
__global__ void mean_kernel(const float* __restrict__ h, float* __restrict__ hg) {
    int b = blockIdx.x, chunk = blockIdx.y, d = threadIdx.x;
    float acc = 0.0f;
    int base = b * L_ + chunk * 256;
    for (int t = 0; t < 256; t++)
        acc += h[(size_t)(base + t) * DM + d];
    atomicAdd(&hg[b * DM + d], acc * (1.0f / L_));
}

// ---------------- host driver ----------------------------------------------------
extern "C" void kernel_launch(void* const* d_in, const int* in_sizes, int n_in,
                              void* d_out, int out_size) {
    const float* x       = (const float*)d_in[0];
    const float* proj_w  = (const float*)d_in[1];
    const float* proj_b  = (const float*)d_in[2];
    const float* ln_w    = (const float*)d_in[3];
    const float* ln_b    = (const float*)d_in[4];
    const float* in_w    = (const float*)d_in[5];
    const float* conv_w  = (const float*)d_in[6];
    const float* conv_b  = (const float*)d_in[7];
    const float* xproj_w = (const float*)d_in[8];
    const float* dt_w    = (const float*)d_in[9];
    const float* dt_b    = (const float*)d_in[10];
    const float* A_log   = (const float*)d_in[11];
    const float* Dp      = (const float*)d_in[12];
    const float* out_w   = (const float*)d_in[13];
    const float* lnout_w = (const float*)d_in[14];
    const float* lnout_b = (const float*)d_in[15];

    float* h  = (float*)d_out;                       // [B,L,128]
    float* hg = h + (size_t)NROWS * DM;              // [B,128]

    float *xn, *xz, *u2, *dbc, *yb, *dec, *snd, *hin;
    cudaGetSymbolAddress((void**)&xn,  g_xn);
    cudaGetSymbolAddress((void**)&xz,  g_xz);
    cudaGetSymbolAddress((void**)&u2,  g_u2);
    cudaGetSymbolAddress((void**)&dbc, g_dbc);
    cudaGetSymbolAddress((void**)&yb,  g_y);
    cudaGetSymbolAddress((void**)&dec, g_dec);
    cudaGetSymbolAddress((void**)&snd, g_snd);
    cudaGetSymbolAddress((void**)&hin, g_hin);

    init_h_kernel<<<(NROWS * DM + 255) / 256, 256>>>(x, proj_w, proj_b, h);
    ln_kernel<<<NROWS / 8, 256>>>(h, ln_w, ln_b, xn, NROWS);

    for (int i = 0; i < 4; i++) {
        gemm_tf32<<<dim3(4, NROWS / TBM), 256>>>(
            xn, in_w + (size_t)i * 512 * DM, xz, NROWS, 512, DM);
        conv_silu_kernel<<<((NROWS / 4) * 64 + 255) / 256, 256>>>(
            xz, conv_w + i * DI * 4, conv_b + i * DI, u2);
        gemm_tf32<<<dim3(1, NROWS / TBM), 256>>>(
            u2, xproj_w + (size_t)i * 40 * DI, dbc, NROWS, 40, DI);
        scan_ph1<<<dim3(NCH, B_), 256>>>(u2, dbc, A_log + i * DI * DS,
                                         dt_w + i * DI * DTR, dt_b + i * DI, dec, snd);
        scan_ph2<<<dim3(B_, (DI * DS) / 256), 256>>>(dec, snd, hin);
        scan_ph3<<<dim3(NCH, B_), 256>>>(u2, dbc, xz, A_log + i * DI * DS,
                                         dt_w + i * DI * DTR, dt_b + i * DI,
                                         Dp + i * DI, hin, yb);
        if (i < 3)
            gemm_out_fused<false><<<dim3(1, NROWS / TBM), 256>>>(
                yb, out_w + (size_t)i * DM * DI, h, xn,
                ln_w + (i + 1) * DM, ln_b + (i + 1) * DM, DI);
        else
            gemm_out_fused<true><<<dim3(1, NROWS / TBM), 256>>>(
                yb, out_w + (size_t)i * DM * DI, h, xn,
                lnout_w, lnout_b, DI);
    }

    zero_hg_kernel<<<(B_ * DM + 255) / 256, 256>>>(hg);
    mean_kernel<<<dim3(B_, L_ / 256), 128>>>(h, hg);
}

// round 5
// speedup vs baseline: 2.1932x; 1.0005x over previous
#include <cuda_runtime.h>
#include <math.h>

#define B_    8
#define L_    8192
#define DM    128
#define DI    256
#define DS    16
#define DTR   8
#define NROWS (B_*L_)          // 65536
#define TC    64               // scan chunk length
#define NCH   (L_/TC)          // 128 chunks

// ---------------- scratch (device globals; no allocation allowed) ----------------
__device__ float g_xn [(size_t)NROWS*DM];     // layernorm output
__device__ float g_xz [(size_t)NROWS*512];    // in_proj output (u|z)
__device__ float g_u2 [(size_t)NROWS*DI];     // conv+silu output
__device__ float g_dbc[(size_t)NROWS*40];     // x_proj output (dt|B|C)
__device__ float g_y  [(size_t)NROWS*DI];     // scan output
__device__ float g_dec[B_*NCH*DI*DS];         // chunk decay products
__device__ float g_snd[B_*NCH*DI*DS];         // chunk end states
__device__ float g_hin[B_*NCH*DI*DS];         // chunk init states

// ---------------- init: h[b,l,d] = sum_c x[b,c,l]*proj_w[d,c] + proj_b[d] --------
__global__ void init_h_kernel(const float* __restrict__ x, const float* __restrict__ pw,
                              const float* __restrict__ pb, float* __restrict__ h) {
    int idx = blockIdx.x * blockDim.x + threadIdx.x;
    if (idx >= NROWS * DM) return;
    int d = idx & (DM - 1);
    int row = idx >> 7;
    int b = row >> 13;
    int l = row & (L_ - 1);
    float acc = pb[d];
#pragma unroll
    for (int c = 0; c < 3; c++)
        acc += x[(b * 3 + c) * L_ + l] * pw[d * 3 + c];
    h[idx] = acc;
}

// ---------------- layernorm: warp per row of 128 (only used once, layer 0) -------
__global__ void ln_kernel(const float* __restrict__ in, const float* __restrict__ w,
                          const float* __restrict__ bias, float* __restrict__ out,
                          int nrows) {
    int gwarp = (blockIdx.x * blockDim.x + threadIdx.x) >> 5;
    int lane  = threadIdx.x & 31;
    if (gwarp >= nrows) return;
    const float4 v = *reinterpret_cast<const float4*>(&in[(size_t)gwarp * DM + lane * 4]);
    float s = v.x + v.y + v.z + v.w;
#pragma unroll
    for (int o = 16; o; o >>= 1) s += __shfl_xor_sync(0xffffffffu, s, o);
    float mu = s * (1.0f / DM);
    float d0 = v.x - mu, d1 = v.y - mu, d2 = v.z - mu, d3 = v.w - mu;
    float q = d0 * d0 + d1 * d1 + d2 * d2 + d3 * d3;
#pragma unroll
    for (int o = 16; o; o >>= 1) q += __shfl_xor_sync(0xffffffffu, q, o);
    float r = rsqrtf(q * (1.0f / DM) + 1e-5f);
    const float4 wv = *reinterpret_cast<const float4*>(&w[lane * 4]);
    const float4 bv = *reinterpret_cast<const float4*>(&bias[lane * 4]);
    float4 o4;
    o4.x = d0 * r * wv.x + bv.x;
    o4.y = d1 * r * wv.y + bv.y;
    o4.z = d2 * r * wv.z + bv.z;
    o4.w = d3 * r * wv.w + bv.w;
    *reinterpret_cast<float4*>(&out[(size_t)gwarp * DM + lane * 4]) = o4;
}

// ---------------- TF32 tensor-core GEMM: C[M,N] = A[M,K] * W[N,K]^T --------------
#define TBM 128
#define TBN 128
#define TBK 32
#define SPITCH (TBM + 4)

__device__ __forceinline__ unsigned f2tf(float x) {
    unsigned r;
    asm("cvt.rna.tf32.f32 %0, %1;" : "=r"(r) : "f"(x));
    return r;
}

// shared mainloop body: accumulates block tile into acc
__device__ __forceinline__ void gemm_mainloop(
    const float* __restrict__ A, const float* __restrict__ W,
    int M, int N, int K, int m0, int n0,
    unsigned* As, unsigned* Ws, float acc[4][4][4]) {
    int tid  = threadIdx.x;
    int warp = tid >> 5;
    int lane = tid & 31;
    int gid  = lane >> 2;
    int tig  = lane & 3;
    int wm = (warp >> 2) * 64;
    int wn = (warp & 3) * 32;

    for (int k0 = 0; k0 < K; k0 += TBK) {
#pragma unroll
        for (int r = 0; r < 4; r++) {
            int linear = tid + r * 256;
            int m = linear >> 3;
            int kq = (linear & 7) * 4;
            float4 v = *reinterpret_cast<const float4*>(&A[(size_t)(m0 + m) * K + k0 + kq]);
            As[(kq + 0) * SPITCH + m] = f2tf(v.x);
            As[(kq + 1) * SPITCH + m] = f2tf(v.y);
            As[(kq + 2) * SPITCH + m] = f2tf(v.z);
            As[(kq + 3) * SPITCH + m] = f2tf(v.w);
        }
#pragma unroll
        for (int r = 0; r < 4; r++) {
            int linear = tid + r * 256;
            int n = linear >> 3;
            int kq = (linear & 7) * 4;
            float4 v = make_float4(0.f, 0.f, 0.f, 0.f);
            if (n0 + n < N)
                v = *reinterpret_cast<const float4*>(&W[(size_t)(n0 + n) * K + k0 + kq]);
            Ws[(kq + 0) * SPITCH + n] = f2tf(v.x);
            Ws[(kq + 1) * SPITCH + n] = f2tf(v.y);
            Ws[(kq + 2) * SPITCH + n] = f2tf(v.z);
            Ws[(kq + 3) * SPITCH + n] = f2tf(v.w);
        }
        __syncthreads();
#pragma unroll
        for (int kk = 0; kk < 4; kk++) {
            unsigned a[4][4], bfr[4][2];
#pragma unroll
            for (int mf = 0; mf < 4; mf++) {
                int rb = wm + mf * 16;
                a[mf][0] = As[(kk * 8 + tig) * SPITCH + rb + gid];
                a[mf][1] = As[(kk * 8 + tig) * SPITCH + rb + gid + 8];
                a[mf][2] = As[(kk * 8 + tig + 4) * SPITCH + rb + gid];
                a[mf][3] = As[(kk * 8 + tig + 4) * SPITCH + rb + gid + 8];
            }
#pragma unroll
            for (int nf = 0; nf < 4; nf++) {
                int nb = wn + nf * 8 + gid;
                bfr[nf][0] = Ws[(kk * 8 + tig) * SPITCH + nb];
                bfr[nf][1] = Ws[(kk * 8 + tig + 4) * SPITCH + nb];
            }
#pragma unroll
            for (int mf = 0; mf < 4; mf++)
#pragma unroll
                for (int nf = 0; nf < 4; nf++) {
                    asm volatile(
                        "mma.sync.aligned.m16n8k8.row.col.f32.tf32.tf32.f32 "
                        "{%0,%1,%2,%3}, {%4,%5,%6,%7}, {%8,%9}, {%0,%1,%2,%3};"
                        : "+f"(acc[mf][nf][0]), "+f"(acc[mf][nf][1]),
                          "+f"(acc[mf][nf][2]), "+f"(acc[mf][nf][3])
                        : "r"(a[mf][0]), "r"(a[mf][1]), "r"(a[mf][2]), "r"(a[mf][3]),
                          "r"(bfr[nf][0]), "r"(bfr[nf][1]));
                }
        }
        __syncthreads();
    }
}

__global__ __launch_bounds__(256) void gemm_tf32(
    const float* __restrict__ A, const float* __restrict__ W,
    float* __restrict__ C, int M, int N, int K) {
    __shared__ unsigned As[TBK * SPITCH];
    __shared__ unsigned Ws[TBK * SPITCH];
    int tid  = threadIdx.x;
    int warp = tid >> 5;
    int lane = tid & 31;
    int gid  = lane >> 2;
    int tig  = lane & 3;
    int wm = (warp >> 2) * 64;
    int wn = (warp & 3) * 32;
    int m0 = blockIdx.y * TBM;
    int n0 = blockIdx.x * TBN;

    float acc[4][4][4];
#pragma unroll
    for (int i = 0; i < 4; i++)
#pragma unroll
        for (int j = 0; j < 4; j++)
#pragma unroll
            for (int r = 0; r < 4; r++) acc[i][j][r] = 0.0f;

    gemm_mainloop(A, W, M, N, K, m0, n0, As, Ws, acc);

#pragma unroll
    for (int mf = 0; mf < 4; mf++) {
        int row0 = m0 + wm + mf * 16 + gid;
#pragma unroll
        for (int nf = 0; nf < 4; nf++) {
            int col = n0 + wn + nf * 8 + tig * 2;
            if (col < N) {
                size_t o0 = (size_t)row0 * N + col;
                size_t o1 = (size_t)(row0 + 8) * N + col;
                C[o0]     = acc[mf][nf][0];
                C[o0 + 1] = acc[mf][nf][1];
                C[o1]     = acc[mf][nf][2];
                C[o1 + 1] = acc[mf][nf][3];
            }
        }
    }
}

// ---------------- out-proj GEMM + residual + fused LayerNorm ---------------------
// N = DM = 128 (one tile) => block owns complete rows. Computes resid = h + A*W^T,
// writes resid to h (unless LAST), then LN(resid) -> xn (or h if LAST).
template <bool LAST>
__global__ __launch_bounds__(256) void gemm_out_fused(
    const float* __restrict__ A, const float* __restrict__ W,
    float* __restrict__ h, float* __restrict__ xn,
    const float* __restrict__ lnw, const float* __restrict__ lnb, int K) {
    __shared__ unsigned As[TBK * SPITCH];
    __shared__ unsigned Ws[TBK * SPITCH];
    __shared__ float red[2][128][4];
    int tid  = threadIdx.x;
    int warp = tid >> 5;
    int lane = tid & 31;
    int gid  = lane >> 2;
    int tig  = lane & 3;
    int wm = (warp >> 2) * 64;
    int wn = (warp & 3) * 32;
    int m0 = blockIdx.y * TBM;

    float acc[4][4][4];
#pragma unroll
    for (int i = 0; i < 4; i++)
#pragma unroll
        for (int j = 0; j < 4; j++)
#pragma unroll
            for (int r = 0; r < 4; r++) acc[i][j][r] = 0.0f;

    gemm_mainloop(A, W, 0, DM, K, m0, 0, As, Ws, acc);

    // residual add (acc becomes resid); write resid to h unless LAST
#pragma unroll
    for (int mf = 0; mf < 4; mf++) {
        int row0 = m0 + wm + mf * 16 + gid;
#pragma unroll
        for (int nf = 0; nf < 4; nf++) {
            int col = wn + nf * 8 + tig * 2;
            size_t o0 = (size_t)row0 * DM + col;
            size_t o1 = (size_t)(row0 + 8) * DM + col;
            acc[mf][nf][0] += h[o0];
            acc[mf][nf][1] += h[o0 + 1];
            acc[mf][nf][2] += h[o1];
            acc[mf][nf][3] += h[o1 + 1];
            if (!LAST) {
                h[o0]     = acc[mf][nf][0];
                h[o0 + 1] = acc[mf][nf][1];
                h[o1]     = acc[mf][nf][2];
                h[o1 + 1] = acc[mf][nf][3];
            }
        }
    }

    // per-row mean/var reduction: tig (shfl) then cross-warp (smem)
#pragma unroll
    for (int mf = 0; mf < 4; mf++) {
#pragma unroll
        for (int half = 0; half < 2; half++) {
            float s = 0.f, q = 0.f;
#pragma unroll
            for (int nf = 0; nf < 4; nf++) {
#pragma unroll
                for (int c = 0; c < 2; c++) {
                    float v = acc[mf][nf][half * 2 + c];
                    s += v; q += v * v;
                }
            }
            s += __shfl_xor_sync(0xffffffffu, s, 1);
            s += __shfl_xor_sync(0xffffffffu, s, 2);
            q += __shfl_xor_sync(0xffffffffu, q, 1);
            q += __shfl_xor_sync(0xffffffffu, q, 2);
            int row = wm + mf * 16 + gid + half * 8;   // local 0..127
            if (tig == 0) {
                red[0][row][warp & 3] = s;
                red[1][row][warp & 3] = q;
            }
        }
    }
    __syncthreads();

#pragma unroll
    for (int mf = 0; mf < 4; mf++) {
#pragma unroll
        for (int half = 0; half < 2; half++) {
            int row = wm + mf * 16 + gid + half * 8;
            float s = red[0][row][0] + red[0][row][1] + red[0][row][2] + red[0][row][3];
            float q = red[1][row][0] + red[1][row][1] + red[1][row][2] + red[1][row][3];
            float mu = s * (1.0f / DM);
            float var = q * (1.0f / DM) - mu * mu;
            float rsig = rsqrtf(var + 1e-5f);
            size_t rbase = (size_t)(m0 + row) * DM;
            float* dst = LAST ? h : xn;
#pragma unroll
            for (int nf = 0; nf < 4; nf++) {
#pragma unroll
                for (int c = 0; c < 2; c++) {
                    int col = wn + nf * 8 + tig * 2 + c;
                    float v = acc[mf][nf][half * 2 + c];
                    dst[rbase + col] = (v - mu) * rsig * lnw[col] + lnb[col];
                }
            }
        }
    }
}

// ---------------- causal depthwise conv1d + silu: 4 timesteps per thread ---------
__global__ void conv_silu_kernel(const float* __restrict__ xz, const float* __restrict__ cw,
                                 const float* __restrict__ cb, float* __restrict__ u2) {
    int idx = blockIdx.x * blockDim.x + threadIdx.x;   // (NROWS/4) * 64
    if (idx >= (NROWS / 4) * 64) return;
    int d4 = idx & 63;
    int g  = idx >> 6;
    int l0 = (g & (L_ / 4 - 1)) * 4;
    int b  = g >> 11;
    int row0 = b * L_ + l0;

    const float4* cw4 = reinterpret_cast<const float4*>(cw);
    float4 t0 = cw4[d4 * 4 + 0];
    float4 t1 = cw4[d4 * 4 + 1];
    float4 t2 = cw4[d4 * 4 + 2];
    float4 t3 = cw4[d4 * 4 + 3];
    float wA[4] = {t0.x, t0.y, t0.z, t0.w};
    float wB[4] = {t1.x, t1.y, t1.z, t1.w};
    float wC[4] = {t2.x, t2.y, t2.z, t2.w};
    float wD[4] = {t3.x, t3.y, t3.z, t3.w};
    float4 bias = reinterpret_cast<const float4*>(cb)[d4];

    float4 v[7];
#pragma unroll
    for (int k = 0; k < 7; k++) {
        if (l0 - 3 + k >= 0)
            v[k] = reinterpret_cast<const float4*>(xz)[(size_t)(row0 - 3 + k) * 128 + d4];
        else
            v[k] = make_float4(0.f, 0.f, 0.f, 0.f);
    }
#pragma unroll
    for (int j = 0; j < 4; j++) {
        float4 acc = bias;
#pragma unroll
        for (int k = 0; k < 4; k++) {
            float4 x = v[j + k];
            acc.x += x.x * wA[k];
            acc.y += x.y * wB[k];
            acc.z += x.z * wC[k];
            acc.w += x.w * wD[k];
        }
        float4 o;
        o.x = acc.x / (1.0f + __expf(-acc.x));
        o.y = acc.y / (1.0f + __expf(-acc.y));
        o.z = acc.z / (1.0f + __expf(-acc.z));
        o.w = acc.w / (1.0f + __expf(-acc.w));
        reinterpret_cast<float4*>(u2)[(size_t)(row0 + j) * 64 + d4] = o;
    }
}

// ---------------- softplus helper -------------------------------------------------
__device__ __forceinline__ float softplusf(float x) {
    return (x > 20.0f) ? x : log1pf(__expf(x));
}

// ---------------- scan phase 1: per-chunk local scan (init=0), dt fused ----------
__global__ void scan_ph1(const float* __restrict__ u2, const float* __restrict__ dbc,
                         const float* __restrict__ Alog,
                         const float* __restrict__ dtw, const float* __restrict__ dtb,
                         float* __restrict__ dec, float* __restrict__ snd) {
    int c = blockIdx.x, b = blockIdx.y, d = threadIdx.x;
    __shared__ float Bsh[TC * DS];
    __shared__ float Dsh[TC * DTR];
    int rb = b * L_ + c * TC;
    for (int idx = d; idx < TC * 24; idx += 256) {
        int t = idx / 24, f = idx % 24;
        float v = dbc[(size_t)(rb + t) * 40 + f];
        if (f < 8) Dsh[t * 8 + f] = v;
        else       Bsh[t * 16 + f - 8] = v;
    }
    float wreg[DTR];
#pragma unroll
    for (int k = 0; k < DTR; k++) wreg[k] = dtw[d * DTR + k];
    float breg = dtb[d];
    float Ar[DS];
    bool fast = true;
#pragma unroll
    for (int s = 0; s < DS; s++) {
        Ar[s] = -__expf(Alog[d * DS + s]);
        fast = fast && (fabsf(Ar[s] + (float)(s + 1)) < 1e-4f * (float)(s + 1));
    }
    __syncthreads();
    float h[DS], cum[DS];
#pragma unroll
    for (int s = 0; s < DS; s++) { h[s] = 0.0f; cum[s] = 1.0f; }
    float sdt = 0.0f;
    for (int t = 0; t < TC; t++) {
        float draw = breg;
#pragma unroll
        for (int k = 0; k < DTR; k++) draw += Dsh[t * 8 + k] * wreg[k];
        float dtv = softplusf(draw);
        float uv  = u2[(size_t)(rb + t) * DI + d];
        float xv = dtv * uv;
        if (fast) {
            float r = __expf(-dtv);
            float p = 1.0f;
            sdt += dtv;
#pragma unroll
            for (int s = 0; s < DS; s++) {
                p *= r;
                h[s] = h[s] * p + xv * Bsh[t * DS + s];
            }
        } else {
#pragma unroll
            for (int s = 0; s < DS; s++) {
                float dA = __expf(dtv * Ar[s]);
                h[s] = h[s] * dA + xv * Bsh[t * DS + s];
                cum[s] *= dA;
            }
        }
    }
    if (fast) {
        float R = __expf(-sdt);
        float p = 1.0f;
#pragma unroll
        for (int s = 0; s < DS; s++) { p *= R; cum[s] = p; }
    }
    size_t base = ((size_t)((b * NCH + c) * DI) + d) * DS;
#pragma unroll
    for (int s = 0; s < DS; s++) { snd[base + s] = h[s]; dec[base + s] = cum[s]; }
}

// ---------------- scan phase 2: sequential combine across chunks -----------------
__global__ void scan_ph2(const float* __restrict__ dec, const float* __restrict__ snd,
                         float* __restrict__ hin) {
    int b = blockIdx.x;
    int t = blockIdx.y * blockDim.x + threadIdx.x;
    float h = 0.0f;
    for (int c = 0; c < NCH; c++) {
        size_t idx = (size_t)(b * NCH + c) * (DI * DS) + t;
        hin[idx] = h;
        h = h * dec[idx] + snd[idx];
    }
}

// ---------------- scan phase 3: full scan with init state, emit y ----------------
__global__ void scan_ph3(const float* __restrict__ u2, const float* __restrict__ dbc,
                         const float* __restrict__ xz, const float* __restrict__ Alog,
                         const float* __restrict__ dtw, const float* __restrict__ dtb,
                         const float* __restrict__ Dp, const float* __restrict__ hin,
                         float* __restrict__ yo) {
    int c = blockIdx.x, b = blockIdx.y, d = threadIdx.x;
    __shared__ float Bsh[TC * DS];
    __shared__ float Csh[TC * DS];
    __shared__ float Dsh[TC * DTR];
    int rb = b * L_ + c * TC;
    for (int idx = d; idx < TC * 40; idx += 256) {
        int t = idx / 40, f = idx % 40;
        float v = dbc[(size_t)(rb + t) * 40 + f];
        if (f < 8)       Dsh[t * 8 + f] = v;
        else if (f < 24) Bsh[t * 16 + f - 8] = v;
        else             Csh[t * 16 + f - 24] = v;
    }
    float wreg[DTR];
#pragma unroll
    for (int k = 0; k < DTR; k++) wreg[k] = dtw[d * DTR + k];
    float breg = dtb[d];
    float Ar[DS];
    bool fast = true;
#pragma unroll
    for (int s = 0; s < DS; s++) {
        Ar[s] = -__expf(Alog[d * DS + s]);
        fast = fast && (fabsf(Ar[s] + (float)(s + 1)) < 1e-4f * (float)(s + 1));
    }
    size_t base = ((size_t)((b * NCH + c) * DI) + d) * DS;
    float h[DS];
#pragma unroll
    for (int s = 0; s < DS; s++) h[s] = hin[base + s];
    __syncthreads();
    float dpv = Dp[d];
    for (int t = 0; t < TC; t++) {
        float draw = breg;
#pragma unroll
        for (int k = 0; k < DTR; k++) draw += Dsh[t * 8 + k] * wreg[k];
        float dtv = softplusf(draw);
        float uv  = u2[(size_t)(rb + t) * DI + d];
        float xv = dtv * uv;
        float y = 0.0f;
        if (fast) {
            float r = __expf(-dtv);
            float p = 1.0f;
#pragma unroll
            for (int s = 0; s < DS; s++) {
                p *= r;
                h[s] = h[s] * p + xv * Bsh[t * DS + s];
                y += h[s] * Csh[t * DS + s];
            }
        } else {
#pragma unroll
            for (int s = 0; s < DS; s++) {
                float dA = __expf(dtv * Ar[s]);
                h[s] = h[s] * dA + xv * Bsh[t * DS + s];
                y += h[s] * Csh[t * DS + s];
            }
        }
        float zv = xz[(size_t)(rb + t) * 512 + 256 + d];
        float sig = 1.0f / (1.0f + __expf(-zv));
        yo[(size_t)(rb + t) * DI + d] = (y + uv * dpv) * (zv * sig);
    }
}

// ---------------- final mean over L ----------------------------------------------
__global__ void zero_hg_kernel(float* __restrict__ hg) {
    int i = blockIdx.x * blockDim.x + threadIdx.x;
    if (i < B_ * DM) hg[i] = 0.0f;
}
__global__ void mean_kernel(const float* __restrict__ h, float* __restrict__ hg) {
    int b = blockIdx.x, chunk = blockIdx.y, d = threadIdx.x;
    float acc = 0.0f;
    int base = b * L_ + chunk * 256;
    for (int t = 0; t < 256; t++)
        acc += h[(size_t)(base + t) * DM + d];
    atomicAdd(&hg[b * DM + d], acc * (1.0f / L_));
}

// ---------------- host driver ----------------------------------------------------
extern "C" void kernel_launch(void* const* d_in, const int* in_sizes, int n_in,
                              void* d_out, int out_size) {
    const float* x       = (const float*)d_in[0];
    const float* proj_w  = (const float*)d_in[1];
    const float* proj_b  = (const float*)d_in[2];
    const float* ln_w    = (const float*)d_in[3];
    const float* ln_b    = (const float*)d_in[4];
    const float* in_w    = (const float*)d_in[5];
    const float* conv_w  = (const float*)d_in[6];
    const float* conv_b  = (const float*)d_in[7];
    const float* xproj_w = (const float*)d_in[8];
    const float* dt_w    = (const float*)d_in[9];
    const float* dt_b    = (const float*)d_in[10];
    const float* A_log   = (const float*)d_in[11];
    const float* Dp      = (const float*)d_in[12];
    const float* out_w   = (const float*)d_in[13];
    const float* lnout_w = (const float*)d_in[14];
    const float* lnout_b = (const float*)d_in[15];

    float* h  = (float*)d_out;                       // [B,L,128]
    float* hg = h + (size_t)NROWS * DM;              // [B,128]

    float *xn, *xz, *u2, *dbc, *yb, *dec, *snd, *hin;
    cudaGetSymbolAddress((void**)&xn,  g_xn);
    cudaGetSymbolAddress((void**)&xz,  g_xz);
    cudaGetSymbolAddress((void**)&u2,  g_u2);
    cudaGetSymbolAddress((void**)&dbc, g_dbc);
    cudaGetSymbolAddress((void**)&yb,  g_y);
    cudaGetSymbolAddress((void**)&dec, g_dec);
    cudaGetSymbolAddress((void**)&snd, g_snd);
    cudaGetSymbolAddress((void**)&hin, g_hin);

    init_h_kernel<<<(NROWS * DM + 255) / 256, 256>>>(x, proj_w, proj_b, h);
    ln_kernel<<<NROWS / 8, 256>>>(h, ln_w, ln_b, xn, NROWS);

    for (int i = 0; i < 4; i++) {
        gemm_tf32<<<dim3(4, NROWS / TBM), 256>>>(
            xn, in_w + (size_t)i * 512 * DM, xz, NROWS, 512, DM);
        conv_silu_kernel<<<((NROWS / 4) * 64 + 255) / 256, 256>>>(
            xz, conv_w + i * DI * 4, conv_b + i * DI, u2);
        gemm_tf32<<<dim3(1, NROWS / TBM), 256>>>(
            u2, xproj_w + (size_t)i * 40 * DI, dbc, NROWS, 40, DI);
        scan_ph1<<<dim3(NCH, B_), 256>>>(u2, dbc, A_log + i * DI * DS,
                                         dt_w + i * DI * DTR, dt_b + i * DI, dec, snd);
        scan_ph2<<<dim3(B_, (DI * DS) / 256), 256>>>(dec, snd, hin);
        scan_ph3<<<dim3(NCH, B_), 256>>>(u2, dbc, xz, A_log + i * DI * DS,
                                         dt_w + i * DI * DTR, dt_b + i * DI,
                                         Dp + i * DI, hin, yb);
        if (i < 3)
            gemm_out_fused<false><<<dim3(1, NROWS / TBM), 256>>>(
                yb, out_w + (size_t)i * DM * DI, h, xn,
                ln_w + (i + 1) * DM, ln_b + (i + 1) * DM, DI);
        else
            gemm_out_fused<true><<<dim3(1, NROWS / TBM), 256>>>(
                yb, out_w + (size_t)i * DM * DI, h, xn,
                lnout_w, lnout_b, DI);
    }

    zero_hg_kernel<<<(B_ * DM + 255) / 256, 256>>>(hg);
    mean_kernel<<<dim3(B_, L_ / 256), 128>>>(h, hg);
}

// round 6
// speedup vs baseline: 2.3928x; 1.0910x over previous
#include <cuda_runtime.h>
#include <math.h>
#include <stdint.h>

#define B_    8
#define L_    8192
#define DM    128
#define DI    256
#define DS    16
#define DTR   8
#define NROWS (B_*L_)          // 65536
#define TC    64               // scan chunk length
#define NCH   (L_/TC)          // 128 chunks

// ---------------- scratch (device globals; no allocation allowed) ----------------
__device__ float g_xn [(size_t)NROWS*DM];     // layernorm output (tf32-rounded)
__device__ float g_xz [(size_t)NROWS*512];    // in_proj output (u|z)
__device__ float g_u2 [(size_t)NROWS*DI];     // conv+silu output (tf32-rounded)
__device__ float g_dbc[(size_t)NROWS*40];     // x_proj output (dt|B|C)
__device__ float g_y  [(size_t)NROWS*DI];     // scan output (tf32-rounded)
__device__ float g_dec[B_*NCH*DI*DS];
__device__ float g_snd[B_*NCH*DI*DS];
__device__ float g_hin[B_*NCH*DI*DS];
// tf32-rounded weights: in_w | xproj_w | out_w
#define WPI 0
#define WPX 262144                 // 4*512*128
#define WPO 303104                 // WPX + 4*40*256
#define WPT 434176                 // WPO + 4*128*256
__device__ float g_wp[WPT];

// ---------------- helpers ----------------------------------------------------------
__device__ __forceinline__ float tf32r(float x) {
    uint32_t r;
    asm("cvt.rna.tf32.f32 %0, %1;" : "=r"(r) : "f"(x));
    return __uint_as_float(r);
}
__device__ __forceinline__ uint32_t s2u(const void* p) {
    uint32_t r;
    asm("{ .reg .u64 t; cvta.to.shared.u64 t, %1; cvt.u32.u64 %0, t; }" : "=r"(r) : "l"(p));
    return r;
}

// ---------------- weight prep: round all GEMM weights to tf32 once ----------------
__global__ void prep_w(const float* __restrict__ in_w, const float* __restrict__ xproj_w,
                       const float* __restrict__ out_w, float* __restrict__ wp) {
    int i = blockIdx.x * blockDim.x + threadIdx.x;
    if (i < WPX)            wp[i] = tf32r(in_w[i]);
    else if (i < WPO)       wp[i] = tf32r(xproj_w[i - WPX]);
    else if (i < WPT)       wp[i] = tf32r(out_w[i - WPO]);
}

// ---------------- init ------------------------------------------------------------
__global__ void init_h_kernel(const float* __restrict__ x, const float* __restrict__ pw,
                              const float* __restrict__ pb, float* __restrict__ h) {
    int idx = blockIdx.x * blockDim.x + threadIdx.x;
    if (idx >= NROWS * DM) return;
    int d = idx & (DM - 1);
    int row = idx >> 7;
    int b = row >> 13;
    int l = row & (L_ - 1);
    float acc = pb[d];
#pragma unroll
    for (int c = 0; c < 3; c++)
        acc += x[(b * 3 + c) * L_ + l] * pw[d * 3 + c];
    h[idx] = acc;
}

// ---------------- layernorm: warp per row (layer-0 only); writes tf32-rounded -----
__global__ void ln_kernel(const float* __restrict__ in, const float* __restrict__ w,
                          const float* __restrict__ bias, float* __restrict__ out,
                          int nrows) {
    int gwarp = (blockIdx.x * blockDim.x + threadIdx.x) >> 5;
    int lane  = threadIdx.x & 31;
    if (gwarp >= nrows) return;
    const float4 v = *reinterpret_cast<const float4*>(&in[(size_t)gwarp * DM + lane * 4]);
    float s = v.x + v.y + v.z + v.w;
#pragma unroll
    for (int o = 16; o; o >>= 1) s += __shfl_xor_sync(0xffffffffu, s, o);
    float mu = s * (1.0f / DM);
    float d0 = v.x - mu, d1 = v.y - mu, d2 = v.z - mu, d3 = v.w - mu;
    float q = d0 * d0 + d1 * d1 + d2 * d2 + d3 * d3;
#pragma unroll
    for (int o = 16; o; o >>= 1) q += __shfl_xor_sync(0xffffffffu, q, o);
    float r = rsqrtf(q * (1.0f / DM) + 1e-5f);
    const float4 wv = *reinterpret_cast<const float4*>(&w[lane * 4]);
    const float4 bv = *reinterpret_cast<const float4*>(&bias[lane * 4]);
    float4 o4;
    o4.x = tf32r(d0 * r * wv.x + bv.x);
    o4.y = tf32r(d1 * r * wv.y + bv.y);
    o4.z = tf32r(d2 * r * wv.z + bv.z);
    o4.w = tf32r(d3 * r * wv.w + bv.w);
    *reinterpret_cast<float4*>(&out[(size_t)gwarp * DM + lane * 4]) = o4;
}

// ---------------- pipelined TF32 GEMM: C[M,N] = A[M,K] * W[N,K]^T ------------------
// 128x128 block tile, TBK=16, cp.async 2-stage. Inputs pre-rounded to tf32.
#define TBM 128
#define TBN 128
#define TBK 16
#define PITCH 20                  // (20m+k) mod 32 distinct over fragment lanes
#define STG (TBM*PITCH)           // floats per stage

__device__ __forceinline__ void prefetch_tile(
    const float* __restrict__ A, const float* __restrict__ W,
    int N, int K, int m0, int n0, float* As, float* Ws, int k0, int tid) {
#pragma unroll
    for (int r = 0; r < 2; r++) {
        int lin = tid + r * 256;            // 0..511
        int row = lin >> 2;                 // 0..127
        int c   = (lin & 3) * 4;            // 0,4,8,12
        uint32_t d = s2u(&As[row * PITCH + c]);
        const float* s = &A[(size_t)(m0 + row) * K + k0 + c];
        asm volatile("cp.async.cg.shared.global [%0], [%1], 16;" :: "r"(d), "l"(s) : "memory");
    }
#pragma unroll
    for (int r = 0; r < 2; r++) {
        int lin = tid + r * 256;
        int row = lin >> 2;
        int c   = (lin & 3) * 4;
        if (n0 + row < N) {
            uint32_t d = s2u(&Ws[row * PITCH + c]);
            const float* s = &W[(size_t)(n0 + row) * K + k0 + c];
            asm volatile("cp.async.cg.shared.global [%0], [%1], 16;" :: "r"(d), "l"(s) : "memory");
        }
    }
}

__device__ __forceinline__ void pipe_mainloop(
    const float* __restrict__ A, const float* __restrict__ W,
    int N, int K, int m0, int n0, float* As, float* Ws, float acc[4][4][4]) {
    int tid  = threadIdx.x;
    int warp = tid >> 5;
    int lane = tid & 31;
    int gid  = lane >> 2;
    int tig  = lane & 3;
    int wm = (warp >> 2) * 64;
    int wn = (warp & 3) * 32;
    int nt = K / TBK;

    prefetch_tile(A, W, N, K, m0, n0, As, Ws, 0, tid);
    asm volatile("cp.async.commit_group;" ::: "memory");
    for (int it = 0; it < nt; it++) {
        if (it + 1 < nt)
            prefetch_tile(A, W, N, K, m0, n0,
                          As + ((it + 1) & 1) * STG, Ws + ((it + 1) & 1) * STG,
                          (it + 1) * TBK, tid);
        asm volatile("cp.async.commit_group;" ::: "memory");
        asm volatile("cp.async.wait_group 1;" ::: "memory");
        __syncthreads();
        const uint32_t* a_s = reinterpret_cast<const uint32_t*>(As + (it & 1) * STG);
        const uint32_t* w_s = reinterpret_cast<const uint32_t*>(Ws + (it & 1) * STG);
#pragma unroll
        for (int kk = 0; kk < 2; kk++) {
            uint32_t a[4][4], b[4][2];
#pragma unroll
            for (int mf = 0; mf < 4; mf++) {
                int rb = wm + mf * 16;
                a[mf][0] = a_s[(rb + gid)     * PITCH + kk * 8 + tig];
                a[mf][1] = a_s[(rb + gid + 8) * PITCH + kk * 8 + tig];
                a[mf][2] = a_s[(rb + gid)     * PITCH + kk * 8 + tig + 4];
                a[mf][3] = a_s[(rb + gid + 8) * PITCH + kk * 8 + tig + 4];
            }
#pragma unroll
            for (int nf = 0; nf < 4; nf++) {
                int nb = wn + nf * 8 + gid;
                b[nf][0] = w_s[nb * PITCH + kk * 8 + tig];
                b[nf][1] = w_s[nb * PITCH + kk * 8 + tig + 4];
            }
#pragma unroll
            for (int mf = 0; mf < 4; mf++)
#pragma unroll
                for (int nf = 0; nf < 4; nf++) {
                    asm volatile(
                        "mma.sync.aligned.m16n8k8.row.col.f32.tf32.tf32.f32 "
                        "{%0,%1,%2,%3}, {%4,%5,%6,%7}, {%8,%9}, {%0,%1,%2,%3};"
                        : "+f"(acc[mf][nf][0]), "+f"(acc[mf][nf][1]),
                          "+f"(acc[mf][nf][2]), "+f"(acc[mf][nf][3])
                        : "r"(a[mf][0]), "r"(a[mf][1]), "r"(a[mf][2]), "r"(a[mf][3]),
                          "r"(b[nf][0]), "r"(b[nf][1]));
                }
        }
        __syncthreads();
    }
}

__global__ __launch_bounds__(256) void gemm_tf32(
    const float* __restrict__ A, const float* __restrict__ W,
    float* __restrict__ C, int M, int N, int K) {
    __shared__ float As[2 * STG];
    __shared__ float Ws[2 * STG];
    int tid  = threadIdx.x;
    int warp = tid >> 5;
    int lane = tid & 31;
    int gid  = lane >> 2;
    int tig  = lane & 3;
    int wm = (warp >> 2) * 64;
    int wn = (warp & 3) * 32;
    int m0 = blockIdx.y * TBM;
    int n0 = blockIdx.x * TBN;

    float acc[4][4][4];
#pragma unroll
    for (int i = 0; i < 4; i++)
#pragma unroll
        for (int j = 0; j < 4; j++)
#pragma unroll
            for (int r = 0; r < 4; r++) acc[i][j][r] = 0.0f;

    pipe_mainloop(A, W, N, K, m0, n0, As, Ws, acc);

#pragma unroll
    for (int mf = 0; mf < 4; mf++) {
        int row0 = m0 + wm + mf * 16 + gid;
#pragma unroll
        for (int nf = 0; nf < 4; nf++) {
            int col = n0 + wn + nf * 8 + tig * 2;
            if (col < N) {
                size_t o0 = (size_t)row0 * N + col;
                size_t o1 = (size_t)(row0 + 8) * N + col;
                C[o0]     = acc[mf][nf][0];
                C[o0 + 1] = acc[mf][nf][1];
                C[o1]     = acc[mf][nf][2];
                C[o1 + 1] = acc[mf][nf][3];
            }
        }
    }
}

// ---------------- out-proj GEMM + residual + fused LayerNorm ----------------------
template <bool LAST>
__global__ __launch_bounds__(256) void gemm_out_fused(
    const float* __restrict__ A, const float* __restrict__ W,
    float* __restrict__ h, float* __restrict__ xn,
    const float* __restrict__ lnw, const float* __restrict__ lnb, int K) {
    __shared__ float As[2 * STG];
    __shared__ float Ws[2 * STG];
    __shared__ float red[2][128][4];
    int tid  = threadIdx.x;
    int warp = tid >> 5;
    int lane = tid & 31;
    int gid  = lane >> 2;
    int tig  = lane & 3;
    int wm = (warp >> 2) * 64;
    int wn = (warp & 3) * 32;
    int m0 = blockIdx.y * TBM;

    float acc[4][4][4];
#pragma unroll
    for (int i = 0; i < 4; i++)
#pragma unroll
        for (int j = 0; j < 4; j++)
#pragma unroll
            for (int r = 0; r < 4; r++) acc[i][j][r] = 0.0f;

    pipe_mainloop(A, W, DM, K, m0, 0, As, Ws, acc);

    // residual add; write resid to h unless LAST
#pragma unroll
    for (int mf = 0; mf < 4; mf++) {
        int row0 = m0 + wm + mf * 16 + gid;
#pragma unroll
        for (int nf = 0; nf < 4; nf++) {
            int col = wn + nf * 8 + tig * 2;
            size_t o0 = (size_t)row0 * DM + col;
            size_t o1 = (size_t)(row0 + 8) * DM + col;
            acc[mf][nf][0] += h[o0];
            acc[mf][nf][1] += h[o0 + 1];
            acc[mf][nf][2] += h[o1];
            acc[mf][nf][3] += h[o1 + 1];
            if (!LAST) {
                h[o0]     = acc[mf][nf][0];
                h[o0 + 1] = acc[mf][nf][1];
                h[o1]     = acc[mf][nf][2];
                h[o1 + 1] = acc[mf][nf][3];
            }
        }
    }

    // per-row mean/var reduction
#pragma unroll
    for (int mf = 0; mf < 4; mf++) {
#pragma unroll
        for (int half = 0; half < 2; half++) {
            float s = 0.f, q = 0.f;
#pragma unroll
            for (int nf = 0; nf < 4; nf++) {
#pragma unroll
                for (int c = 0; c < 2; c++) {
                    float v = acc[mf][nf][half * 2 + c];
                    s += v; q += v * v;
                }
            }
            s += __shfl_xor_sync(0xffffffffu, s, 1);
            s += __shfl_xor_sync(0xffffffffu, s, 2);
            q += __shfl_xor_sync(0xffffffffu, q, 1);
            q += __shfl_xor_sync(0xffffffffu, q, 2);
            int row = wm + mf * 16 + gid + half * 8;
            if (tig == 0) {
                red[0][row][warp & 3] = s;
                red[1][row][warp & 3] = q;
            }
        }
    }
    __syncthreads();

#pragma unroll
    for (int mf = 0; mf < 4; mf++) {
#pragma unroll
        for (int half = 0; half < 2; half++) {
            int row = wm + mf * 16 + gid + half * 8;
            float s = red[0][row][0] + red[0][row][1] + red[0][row][2] + red[0][row][3];
            float q = red[1][row][0] + red[1][row][1] + red[1][row][2] + red[1][row][3];
            float mu = s * (1.0f / DM);
            float var = q * (1.0f / DM) - mu * mu;
            float rsig = rsqrtf(var + 1e-5f);
            size_t rbase = (size_t)(m0 + row) * DM;
#pragma unroll
            for (int nf = 0; nf < 4; nf++) {
#pragma unroll
                for (int c = 0; c < 2; c++) {
                    int col = wn + nf * 8 + tig * 2 + c;
                    float v = (acc[mf][nf][half * 2 + c] - mu) * rsig * lnw[col] + lnb[col];
                    if (LAST) h[rbase + col] = v;           // final output: full fp32
                    else      xn[rbase + col] = tf32r(v);   // next GEMM input
                }
            }
        }
    }
}

// ---------------- causal depthwise conv1d + silu (4 timesteps/thread) -------------
__global__ void conv_silu_kernel(const float* __restrict__ xz, const float* __restrict__ cw,
                                 const float* __restrict__ cb, float* __restrict__ u2) {
    int idx = blockIdx.x * blockDim.x + threadIdx.x;
    if (idx >= (NROWS / 4) * 64) return;
    int d4 = idx & 63;
    int g  = idx >> 6;
    int l0 = (g & (L_ / 4 - 1)) * 4;
    int b  = g >> 11;
    int row0 = b * L_ + l0;

    const float4* cw4 = reinterpret_cast<const float4*>(cw);
    float4 t0 = cw4[d4 * 4 + 0];
    float4 t1 = cw4[d4 * 4 + 1];
    float4 t2 = cw4[d4 * 4 + 2];
    float4 t3 = cw4[d4 * 4 + 3];
    float wA[4] = {t0.x, t0.y, t0.z, t0.w};
    float wB[4] = {t1.x, t1.y, t1.z, t1.w};
    float wC[4] = {t2.x, t2.y, t2.z, t2.w};
    float wD[4] = {t3.x, t3.y, t3.z, t3.w};
    float4 bias = reinterpret_cast<const float4*>(cb)[d4];

    float4 v[7];
#pragma unroll
    for (int k = 0; k < 7; k++) {
        if (l0 - 3 + k >= 0)
            v[k] = reinterpret_cast<const float4*>(xz)[(size_t)(row0 - 3 + k) * 128 + d4];
        else
            v[k] = make_float4(0.f, 0.f, 0.f, 0.f);
    }
#pragma unroll
    for (int j = 0; j < 4; j++) {
        float4 acc = bias;
#pragma unroll
        for (int k = 0; k < 4; k++) {
            float4 x = v[j + k];
            acc.x += x.x * wA[k];
            acc.y += x.y * wB[k];
            acc.z += x.z * wC[k];
            acc.w += x.w * wD[k];
        }
        float4 o;
        o.x = tf32r(acc.x / (1.0f + __expf(-acc.x)));
        o.y = tf32r(acc.y / (1.0f + __expf(-acc.y)));
        o.z = tf32r(acc.z / (1.0f + __expf(-acc.z)));
        o.w = tf32r(acc.w / (1.0f + __expf(-acc.w)));
        reinterpret_cast<float4*>(u2)[(size_t)(row0 + j) * 64 + d4] = o;
    }
}

// ---------------- softplus helper --------------------------------------------------
__device__ __forceinline__ float softplusf(float x) {
    return (x > 20.0f) ? x : log1pf(__expf(x));
}

// ---------------- scan phase 1 ------------------------------------------------------
__global__ void scan_ph1(const float* __restrict__ u2, const float* __restrict__ dbc,
                         const float* __restrict__ Alog,
                         const float* __restrict__ dtw, const float* __restrict__ dtb,
                         float* __restrict__ dec, float* __restrict__ snd) {
    int c = blockIdx.x, b = blockIdx.y, d = threadIdx.x;
    __shared__ float Bsh[TC * DS];
    __shared__ float Dsh[TC * DTR];
    int rb = b * L_ + c * TC;
    for (int idx = d; idx < TC * 24; idx += 256) {
        int t = idx / 24, f = idx % 24;
        float v = dbc[(size_t)(rb + t) * 40 + f];
        if (f < 8) Dsh[t * 8 + f] = v;
        else       Bsh[t * 16 + f - 8] = v;
    }
    float wreg[DTR];
#pragma unroll
    for (int k = 0; k < DTR; k++) wreg[k] = dtw[d * DTR + k];
    float breg = dtb[d];
    float Ar[DS];
    bool fast = true;
#pragma unroll
    for (int s = 0; s < DS; s++) {
        Ar[s] = -__expf(Alog[d * DS + s]);
        fast = fast && (fabsf(Ar[s] + (float)(s + 1)) < 1e-4f * (float)(s + 1));
    }
    __syncthreads();
    float h[DS], cum[DS];
#pragma unroll
    for (int s = 0; s < DS; s++) { h[s] = 0.0f; cum[s] = 1.0f; }
    float sdt = 0.0f;
    for (int t = 0; t < TC; t++) {
        float draw = breg;
#pragma unroll
        for (int k = 0; k < DTR; k++) draw += Dsh[t * 8 + k] * wreg[k];
        float dtv = softplusf(draw);
        float uv  = u2[(size_t)(rb + t) * DI + d];
        float xv = dtv * uv;
        if (fast) {
            float r = __expf(-dtv);
            float p = 1.0f;
            sdt += dtv;
#pragma unroll
            for (int s = 0; s < DS; s++) {
                p *= r;
                h[s] = h[s] * p + xv * Bsh[t * DS + s];
            }
        } else {
#pragma unroll
            for (int s = 0; s < DS; s++) {
                float dA = __expf(dtv * Ar[s]);
                h[s] = h[s] * dA + xv * Bsh[t * DS + s];
                cum[s] *= dA;
            }
        }
    }
    if (fast) {
        float R = __expf(-sdt);
        float p = 1.0f;
#pragma unroll
        for (int s = 0; s < DS; s++) { p *= R; cum[s] = p; }
    }
    size_t base = ((size_t)((b * NCH + c) * DI) + d) * DS;
#pragma unroll
    for (int s = 0; s < DS; s++) { snd[base + s] = h[s]; dec[base + s] = cum[s]; }
}

// ---------------- scan phase 2 ------------------------------------------------------
__global__ void scan_ph2(const float* __restrict__ dec, const float* __restrict__ snd,
                         float* __restrict__ hin) {
    int b = blockIdx.x;
    int t = blockIdx.y * blockDim.x + threadIdx.x;
    float h = 0.0f;
    for (int c = 0; c < NCH; c++) {
        size_t idx = (size_t)(b * NCH + c) * (DI * DS) + t;
        hin[idx] = h;
        h = h * dec[idx] + snd[idx];
    }
}

// ---------------- scan phase 3 ------------------------------------------------------
__global__ void scan_ph3(const float* __restrict__ u2, const float* __restrict__ dbc,
                         const float* __restrict__ xz, const float* __restrict__ Alog,
                         const float* __restrict__ dtw, const float* __restrict__ dtb,
                         const float* __restrict__ Dp, const float* __restrict__ hin,
                         float* __restrict__ yo) {
    int c = blockIdx.x, b = blockIdx.y, d = threadIdx.x;
    __shared__ float Bsh[TC * DS];
    __shared__ float Csh[TC * DS];
    __shared__ float Dsh[TC * DTR];
    int rb = b * L_ + c * TC;
    for (int idx = d; idx < TC * 40; idx += 256) {
        int t = idx / 40, f = idx % 40;
        float v = dbc[(size_t)(rb + t) * 40 + f];
        if (f < 8)       Dsh[t * 8 + f] = v;
        else if (f < 24) Bsh[t * 16 + f - 8] = v;
        else             Csh[t * 16 + f - 24] = v;
    }
    float wreg[DTR];
#pragma unroll
    for (int k = 0; k < DTR; k++) wreg[k] = dtw[d * DTR + k];
    float breg = dtb[d];
    float Ar[DS];
    bool fast = true;
#pragma unroll
    for (int s = 0; s < DS; s++) {
        Ar[s] = -__expf(Alog[d * DS + s]);
        fast = fast && (fabsf(Ar[s] + (float)(s + 1)) < 1e-4f * (float)(s + 1));
    }
    size_t base = ((size_t)((b * NCH + c) * DI) + d) * DS;
    float h[DS];
#pragma unroll
    for (int s = 0; s < DS; s++) h[s] = hin[base + s];
    __syncthreads();
    float dpv = Dp[d];
    for (int t = 0; t < TC; t++) {
        float draw = breg;
#pragma unroll
        for (int k = 0; k < DTR; k++) draw += Dsh[t * 8 + k] * wreg[k];
        float dtv = softplusf(draw);
        float uv  = u2[(size_t)(rb + t) * DI + d];
        float xv = dtv * uv;
        float y = 0.0f;
        if (fast) {
            float r = __expf(-dtv);
            float p = 1.0f;
#pragma unroll
            for (int s = 0; s < DS; s++) {
                p *= r;
                h[s] = h[s] * p + xv * Bsh[t * DS + s];
                y += h[s] * Csh[t * DS + s];
            }
        } else {
#pragma unroll
            for (int s = 0; s < DS; s++) {
                float dA = __expf(dtv * Ar[s]);
                h[s] = h[s] * dA + xv * Bsh[t * DS + s];
                y += h[s] * Csh[t * DS + s];
            }
        }
        float zv = xz[(size_t)(rb + t) * 512 + 256 + d];
        float sig = 1.0f / (1.0f + __expf(-zv));
        yo[(size_t)(rb + t) * DI + d] = tf32r((y + uv * dpv) * (zv * sig));
    }
}

// ---------------- final mean over L ------------------------------------------------
__global__ void zero_hg_kernel(float* __restrict__ hg) {
    int i = blockIdx.x * blockDim.x + threadIdx.x;
    if (i < B_ * DM) hg[i] = 0.0f;
}
__global__ void mean_kernel(const float* __restrict__ h, float* __restrict__ hg) {
    int b = blockIdx.x, chunk = blockIdx.y, d = threadIdx.x;
    float acc = 0.0f;
    int base = b * L_ + chunk * 256;
    for (int t = 0; t < 256; t++)
        acc += h[(size_t)(base + t) * DM + d];
    atomicAdd(&hg[b * DM + d], acc * (1.0f / L_));
}

// ---------------- host driver ------------------------------------------------------
extern "C" void kernel_launch(void* const* d_in, const int* in_sizes, int n_in,
                              void* d_out, int out_size) {
    const float* x       = (const float*)d_in[0];
    const float* proj_w  = (const float*)d_in[1];
    const float* proj_b  = (const float*)d_in[2];
    const float* ln_w    = (const float*)d_in[3];
    const float* ln_b    = (const float*)d_in[4];
    const float* in_w    = (const float*)d_in[5];
    const float* conv_w  = (const float*)d_in[6];
    const float* conv_b  = (const float*)d_in[7];
    const float* xproj_w = (const float*)d_in[8];
    const float* dt_w    = (const float*)d_in[9];
    const float* dt_b    = (const float*)d_in[10];
    const float* A_log   = (const float*)d_in[11];
    const float* Dp      = (const float*)d_in[12];
    const float* out_w   = (const float*)d_in[13];
    const float* lnout_w = (const float*)d_in[14];
    const float* lnout_b = (const float*)d_in[15];

    float* h  = (float*)d_out;                       // [B,L,128]
    float* hg = h + (size_t)NROWS * DM;              // [B,128]

    float *xn, *xz, *u2, *dbc, *yb, *dec, *snd, *hin, *wp;
    cudaGetSymbolAddress((void**)&xn,  g_xn);
    cudaGetSymbolAddress((void**)&xz,  g_xz);
    cudaGetSymbolAddress((void**)&u2,  g_u2);
    cudaGetSymbolAddress((void**)&dbc, g_dbc);
    cudaGetSymbolAddress((void**)&yb,  g_y);
    cudaGetSymbolAddress((void**)&dec, g_dec);
    cudaGetSymbolAddress((void**)&snd, g_snd);
    cudaGetSymbolAddress((void**)&hin, g_hin);
    cudaGetSymbolAddress((void**)&wp,  g_wp);

    prep_w<<<(WPT + 255) / 256, 256>>>(in_w, xproj_w, out_w, wp);
    init_h_kernel<<<(NROWS * DM + 255) / 256, 256>>>(x, proj_w, proj_b, h);
    ln_kernel<<<NROWS / 8, 256>>>(h, ln_w, ln_b, xn, NROWS);

    for (int i = 0; i < 4; i++) {
        gemm_tf32<<<dim3(4, NROWS / TBM), 256>>>(
            xn, wp + WPI + (size_t)i * 512 * DM, xz, NROWS, 512, DM);
        conv_silu_kernel<<<((NROWS / 4) * 64 + 255) / 256, 256>>>(
            xz, conv_w + i * DI * 4, conv_b + i * DI, u2);
        gemm_tf32<<<dim3(1, NROWS / TBM), 256>>>(
            u2, wp + WPX + (size_t)i * 40 * DI, dbc, NROWS, 40, DI);
        scan_ph1<<<dim3(NCH, B_), 256>>>(u2, dbc, A_log + i * DI * DS,
                                         dt_w + i * DI * DTR, dt_b + i * DI, dec, snd);
        scan_ph2<<<dim3(B_, (DI * DS) / 256), 256>>>(dec, snd, hin);
        scan_ph3<<<dim3(NCH, B_), 256>>>(u2, dbc, xz, A_log + i * DI * DS,
                                         dt_w + i * DI * DTR, dt_b + i * DI,
                                         Dp + i * DI, hin, yb);
        if (i < 3)
            gemm_out_fused<false><<<dim3(1, NROWS / TBM), 256>>>(
                yb, wp + WPO + (size_t)i * DM * DI, h, xn,
                ln_w + (i + 1) * DM, ln_b + (i + 1) * DM, DI);
        else
            gemm_out_fused<true><<<dim3(1, NROWS / TBM), 256>>>(
                yb, wp + WPO + (size_t)i * DM * DI, h, xn,
                lnout_w, lnout_b, DI);
    }

    zero_hg_kernel<<<(B_ * DM + 255) / 256, 256>>>(hg);
    mean_kernel<<<dim3(B_, L_ / 256), 128>>>(h, hg);
}